// round 14
// baseline (speedup 1.0000x reference)
#include <cuda_runtime.h>
#include <cuda_fp16.h>
#include <math.h>
#include <stdint.h>

#define Bn   32
#define Sn   64
#define Tn   64
#define EMBn 256
#define HIDn 512
#define VOCn 32000
#define KV   1024      // 2*HID

#define NBLK  128      // barrier participants
#define EXTRA 20       // spare blocks doing W-split
#define NTHR  256

// vocab GEMM tiling
#define BKv   64
#define NKC   (KV / BKv)              // 16 k-chunks
#define BLKB  (128 * BKv * 2)         // 16384 bytes per 128x64 fp16 tile block
#define STGB  (2 * BLKB)              // 32768 bytes per stage (Ah, Wh)

// dynamic smem layout for decoder_persistent (floats)
#define SX_F   (2 * Bn * 132)         // 8448
#define W0_F   (3 * 4 * 768)          // 9216
#define U0_F   (3 * 4 * 512)          // 6144
#define W1_F   (3 * 4 * 512)
#define U1_F   (3 * 4 * 512)
#define WQ_F   (4 * 512)              // 2048
#define RED_F  (2 * 4 * 4 * 32)       // 1024
#define MISC_F 96                     // 32 int tok + 64 float sA
#define DEC_SMEM_F (SX_F + W0_F + U0_F + W1_F + U1_F + WQ_F + RED_F + MISC_F)
#define DEC_SMEM_B (DEC_SMEM_F * 4)   // 157056 bytes

// ---------------- scratch state (device globals; no allocation) ----------------
__device__ __align__(16) float g_kproj[Bn * Sn * HIDn];
__device__ __align__(16) float g_h0[2][Bn * HIDn];
__device__ __align__(16) float g_h1[2][Bn * HIDn];
__device__ __align__(16) float g_ctx[2][Bn * HIDn];
__device__ __align__(16) float g_q[Bn * HIDn];
__device__ __align__(16) float g_e[Bn * Sn];
__device__ __align__(16) float g_dc[Bn * Tn * 2 * HIDn];

// tiled+swizzled fp16 panels: [row_tile][k_chunk][16KB block]
__device__ __align__(1024) __half g_wh[(size_t)VOCn * KV];
__device__ __align__(1024) __half g_ah[Bn * Tn * KV];

// contention-free barrier state (owner-written flags; replay-safe epochs)
__device__ volatile unsigned g_flags[NBLK];
__device__ volatile unsigned g_rel;

// ================= helpers =================
__device__ __forceinline__ uint32_t smem_u32(const void* p) {
    uint32_t a;
    asm("{ .reg .u64 t; cvta.to.shared.u64 t, %1; cvt.u32.u64 %0, t; }" : "=r"(a) : "l"(p));
    return a;
}

#define MBAR_INIT(addr, cnt) \
    asm volatile("mbarrier.init.shared.b64 [%0], %1;" :: "r"(addr), "r"(cnt) : "memory")
#define MBAR_EXPECT_TX(addr, bytes) \
    asm volatile("mbarrier.arrive.expect_tx.shared.b64 _, [%0], %1;" :: "r"(addr), "r"(bytes) : "memory")
#define MBAR_WAIT(addr, parity) do {                                            \
    uint32_t _m = (addr), _p = (parity), _d;                                    \
    asm volatile("{\n\t.reg .pred p;\n\t"                                       \
        "mbarrier.try_wait.parity.acquire.cta.shared::cta.b64 p, [%1], %2;\n\t" \
        "selp.b32 %0, 1, 0, p;\n\t}" : "=r"(_d) : "r"(_m), "r"(_p) : "memory"); \
    if (!_d) {                                                                  \
        asm volatile("{\n\t.reg .pred P1;\n\tWL_%=:\n\t"                        \
            "mbarrier.try_wait.parity.acquire.cta.shared::cta.b64 P1, [%0], %1, 0x989680;\n\t" \
            "@P1 bra.uni WD_%=;\n\tbra.uni WL_%=;\n\tWD_%=:\n\t}"               \
            :: "r"(_m), "r"(_p) : "memory");                                    \
    } } while (0)

__device__ __forceinline__ void bulk_g2s(uint32_t dst, const void* src,
                                         uint32_t bytes, uint32_t bar) {
    asm volatile(
        "cp.async.bulk.shared::cluster.global.mbarrier::complete_tx::bytes "
        "[%0], [%1], %2, [%3];"
        :: "r"(dst), "l"(src), "r"(bytes), "r"(bar) : "memory");
}

__device__ __forceinline__ void ldm4(uint32_t& r0, uint32_t& r1, uint32_t& r2,
                                     uint32_t& r3, uint32_t a) {
    asm volatile("ldmatrix.sync.aligned.m8n8.x4.shared.b16 {%0,%1,%2,%3}, [%4];"
                 : "=r"(r0), "=r"(r1), "=r"(r2), "=r"(r3) : "r"(a));
}

__device__ __forceinline__ void mma_f16(float* c, const uint32_t* a,
                                        uint32_t b0, uint32_t b1) {
    asm volatile(
        "mma.sync.aligned.m16n8k16.row.col.f32.f16.f16.f32 "
        "{%0,%1,%2,%3}, {%4,%5,%6,%7}, {%8,%9}, {%0,%1,%2,%3};"
        : "+f"(c[0]), "+f"(c[1]), "+f"(c[2]), "+f"(c[3])
        : "r"(a[0]), "r"(a[1]), "r"(a[2]), "r"(a[3]), "r"(b0), "r"(b1));
}

__device__ __forceinline__ float tanh_fast(float x) {
    float y;
    asm("tanh.approx.f32 %0, %1;" : "=f"(y) : "f"(x));
    return y;
}

// ---- packed fp32x2 FMA (sm_100+ base feature; PTX-only path) ----
__device__ __forceinline__ void fma2(unsigned long long& a,
                                     unsigned long long x, unsigned long long w) {
    asm("fma.rn.f32x2 %0, %1, %2, %0;" : "+l"(a) : "l"(x), "l"(w));
}
__device__ __forceinline__ float up_sum(unsigned long long a) {
    unsigned lo, hi;
    asm("mov.b64 {%0, %1}, %2;" : "=r"(lo), "=r"(hi) : "l"(a));
    return __uint_as_float(lo) + __uint_as_float(hi);
}
__device__ __forceinline__ unsigned long long dup2(float v) {
    unsigned long long d;
    asm("mov.b64 %0, {%1, %1};" : "=l"(d) : "r"(__float_as_uint(v)));
    return d;
}

// swizzle within a 16KB tile block (128 rows x 128 bytes): chunk' = chunk ^ (row&7)
__device__ __forceinline__ uint32_t swz(uint32_t off) {
    return off ^ (((off >> 7) & 7u) << 4);
}

// ================= split fp32 -> fp16 hi, tiled + swizzled (A panels) =========
__global__ __launch_bounds__(256) void split_h_kernel(
    const float* __restrict__ src, __half* __restrict__ hi, int nchunks)
{
    int id = blockIdx.x * 256 + threadIdx.x;
    if (id >= nchunks) return;
    int n  = id >> 7;
    int k0 = (id & 127) * 8;
    const float* s = src + (size_t)n * KV + k0;
    float4 x0 = *(const float4*)s;
    float4 x1 = *(const float4*)(s + 4);
    float xs[8] = {x0.x, x0.y, x0.z, x0.w, x1.x, x1.y, x1.z, x1.w};

    uint32_t hw[4];
#pragma unroll
    for (int i = 0; i < 4; i++) {
        __half2 hp = __halves2half2(__float2half_rn(xs[2 * i]),
                                    __float2half_rn(xs[2 * i + 1]));
        hw[i] = *(uint32_t*)&hp;
    }

    int nt = n >> 7, r = n & 127, kc = k0 >> 6;
    uint32_t off = swz((uint32_t)(r * 128 + (k0 & 63) * 2));
    size_t blk = ((size_t)nt * NKC + kc) * BLKB;
    *(uint4*)((char*)hi + blk + off) = make_uint4(hw[0], hw[1], hw[2], hw[3]);
}

// ================= HMMA fp16 1-term vocab GEMM (TMA-bulk, 2-stage) ============
__global__ __launch_bounds__(256) void hmma_gemm_vocab(
    const float* __restrict__ bias, float* __restrict__ C)
{
    extern __shared__ __align__(128) char sm[];
    __shared__ __align__(8) uint64_t mbar[2];
    __shared__ float sBias[128];

    const int tid  = threadIdx.x;
    const int wid  = tid >> 5;
    const int lane = tid & 31;
    const int m_t = blockIdx.x, n_t = blockIdx.y;
    const int m0 = m_t * 128,   n0 = n_t * 128;
    const int warp_m = wid & 1;
    const int warp_n = wid >> 1;

    if (tid < 128) sBias[tid] = bias[n0 + tid];

    const uint32_t smb = smem_u32(sm);
    const uint32_t mb  = smem_u32(mbar);

    const char* gA = (const char*)g_ah + (size_t)m_t * NKC * BLKB;
    const char* gH = (const char*)g_wh + (size_t)n_t * NKC * BLKB;

    if (tid == 0) { MBAR_INIT(mb, 1); MBAR_INIT(mb + 8, 1); }
    __syncthreads();

    auto issue = [&](int s, int buf) {
        uint32_t d   = smb + buf * STGB;
        uint32_t bar = mb + buf * 8;
        MBAR_EXPECT_TX(bar, (uint32_t)STGB);
        bulk_g2s(d,        gA + (size_t)s * BLKB, BLKB, bar);
        bulk_g2s(d + BLKB, gH + (size_t)s * BLKB, BLKB, bar);
    };
    if (tid == 0) issue(0, 0);

    float acc[4][4][4];
#pragma unroll
    for (int mt = 0; mt < 4; mt++)
#pragma unroll
        for (int nt = 0; nt < 4; nt++)
#pragma unroll
            for (int r = 0; r < 4; r++) acc[mt][nt][r] = 0.f;

    const int a_row = warp_m * 64 + (lane & 15);
    const int a_cb  = (lane >> 4) * 16;
    const int b_row = warp_n * 32 + ((lane >> 4) << 3) + (lane & 7);
    const int b_cb  = ((lane >> 3) & 1) * 16;

    for (int s = 0; s < NKC; s++) {
        const int buf = s & 1;
        MBAR_WAIT(mb + buf * 8, (uint32_t)((s >> 1) & 1));
        if (tid == 0 && s + 1 < NKC) issue(s + 1, buf ^ 1);

        const uint32_t sA  = smb + buf * STGB;
        const uint32_t sWh = sA + BLKB;

#pragma unroll
        for (int koff = 0; koff < BKv; koff += 16) {
            uint32_t ah[4][4], bh[2][4];
#pragma unroll
            for (int mt = 0; mt < 4; mt++) {
                uint32_t off = swz((uint32_t)((a_row + mt * 16) * 128 +
                                              a_cb + koff * 2));
                ldm4(ah[mt][0], ah[mt][1], ah[mt][2], ah[mt][3], sA + off);
            }
#pragma unroll
            for (int p = 0; p < 2; p++) {
                uint32_t off = swz((uint32_t)((b_row + p * 16) * 128 +
                                              b_cb + koff * 2));
                ldm4(bh[p][0], bh[p][1], bh[p][2], bh[p][3], sWh + off);
            }
#pragma unroll
            for (int mt = 0; mt < 4; mt++) {
#pragma unroll
                for (int nt = 0; nt < 4; nt++) {
                    int p = nt >> 1, h = (nt & 1) * 2;
                    mma_f16(acc[mt][nt], ah[mt], bh[p][h], bh[p][h + 1]);
                }
            }
        }
        __syncthreads();
    }

    const int er = (lane >> 2);
    const int ec = (lane & 3) * 2;
#pragma unroll
    for (int mt = 0; mt < 4; mt++) {
#pragma unroll
        for (int nt = 0; nt < 4; nt++) {
            int row  = m0 + warp_m * 64 + mt * 16 + er;
            int colL = warp_n * 32 + nt * 8 + ec;
            int col  = n0 + colL;
            float2 o0, o1;
            o0.x = acc[mt][nt][0] + sBias[colL];
            o0.y = acc[mt][nt][1] + sBias[colL + 1];
            o1.x = acc[mt][nt][2] + sBias[colL];
            o1.y = acc[mt][nt][3] + sBias[colL + 1];
            *(float2*)(C + (size_t)row * VOCn + col)       = o0;
            *(float2*)(C + (size_t)(row + 8) * VOCn + col) = o1;
        }
    }
}

// ---------------- contention-free grid barrier (flags + master block) ---------
__device__ __forceinline__ void gsync(unsigned e) {
    __syncthreads();
    const int tid = threadIdx.x;
    const int bid = blockIdx.x;
    if (tid == 0) { __threadfence(); g_flags[bid] = e; }
    if (bid == 0) {
        if (tid < NBLK) { while (g_flags[tid] != e) { } }
        __syncthreads();
        if (tid == 0) { __threadfence(); g_rel = e; }
    } else {
        if (tid == 0) { while (g_rel != e) { } __threadfence(); }
    }
    __syncthreads();
}

// ---------------- packed dot helpers ----------------
__device__ __forceinline__ void triple16p(const float* __restrict__ sx,
    const float* __restrict__ w0, const float* __restrict__ w1,
    const float* __restrict__ w2,
    unsigned long long& a0, unsigned long long& a1, unsigned long long& a2)
{
#pragma unroll
    for (int i = 0; i < 16; i++) {
        ulonglong2 x = *(const ulonglong2*)(sx + i * 4);
        ulonglong2 u = *(const ulonglong2*)(w0 + i * 4);
        ulonglong2 v = *(const ulonglong2*)(w1 + i * 4);
        ulonglong2 s = *(const ulonglong2*)(w2 + i * 4);
        fma2(a0, x.x, u.x); fma2(a0, x.y, u.y);
        fma2(a1, x.x, v.x); fma2(a1, x.y, v.y);
        fma2(a2, x.x, s.x); fma2(a2, x.y, s.y);
    }
}
__device__ __forceinline__ void single16p(const float* __restrict__ sx,
    const float* __restrict__ w0, unsigned long long& a0)
{
#pragma unroll
    for (int i = 0; i < 16; i++) {
        ulonglong2 x = *(const ulonglong2*)(sx + i * 4);
        ulonglong2 u = *(const ulonglong2*)(w0 + i * 4);
        fma2(a0, x.x, u.x); fma2(a0, x.y, u.y);
    }
}

// ---------------- persistent recurrence kernel (+W-split on spare blocks) -----
// 256 threads: 8 warps = 4 j (jl) x 2 k-halves (khalf). lane = batch.
// Weight slices for this block live in dynamic SMEM (loaded once).
__global__ __launch_bounds__(NTHR, 1) void decoder_persistent(
    const float* __restrict__ enc, const unsigned char* __restrict__ mask,
    const int* __restrict__ tgt, const float* __restrict__ emb,
    const float* __restrict__ Wih0, const float* __restrict__ Whh0,
    const float* __restrict__ bih0, const float* __restrict__ bhh0,
    const float* __restrict__ Wih1, const float* __restrict__ Whh1,
    const float* __restrict__ bih1, const float* __restrict__ bhh1,
    const float* __restrict__ Wq, const float* __restrict__ vvec,
    const float* __restrict__ Wout)
{
    const int tid = threadIdx.x;
    const int bid = blockIdx.x;

    // ===== spare blocks: stream W_out -> fp16 tiled/swizzled panels =====
    if (bid >= NBLK) {
        const int sp  = bid - NBLK;               // 0..EXTRA-1
        const int nch = VOCn * (KV / 8);          // 4.096M 16B-chunks
        for (int id = sp * NTHR + tid; id < nch; id += EXTRA * NTHR) {
            int n  = id >> 7;
            int k0 = (id & 127) * 8;
            const float* s = Wout + (size_t)n * KV + k0;
            float4 x0 = __ldcs((const float4*)s);
            float4 x1 = __ldcs((const float4*)(s + 4));
            float xs[8] = {x0.x, x0.y, x0.z, x0.w, x1.x, x1.y, x1.z, x1.w};
            uint32_t hw[4];
#pragma unroll
            for (int i = 0; i < 4; i++) {
                __half2 hp = __halves2half2(__float2half_rn(xs[2 * i]),
                                            __float2half_rn(xs[2 * i + 1]));
                hw[i] = *(uint32_t*)&hp;
            }
            int nt = n >> 7, r = n & 127, kc = k0 >> 6;
            uint32_t off = swz((uint32_t)(r * 128 + (k0 & 63) * 2));
            size_t blk = ((size_t)nt * NKC + kc) * BLKB;
            float4 ov = make_float4(__uint_as_float(hw[0]), __uint_as_float(hw[1]),
                                    __uint_as_float(hw[2]), __uint_as_float(hw[3]));
            __stcs((float4*)((char*)g_wh + blk + off), ov);
        }
        return;
    }

    // ===== barrier-participating blocks: the recurrence =====
    extern __shared__ __align__(16) float dsm[];
    float (*sX)[Bn][132] = (float (*)[Bn][132])dsm;            // SX_F
    float* sW0   = dsm + SX_F;                                 // [g][jl][768]
    float* sU0   = sW0 + W0_F;                                 // [g][jl][512]
    float* sW1   = sU0 + U0_F;
    float* sU1   = sW1 + W1_F;
    float* sWq   = sU1 + U1_F;                                 // [jl][512]
    float* sredf = sWq + WQ_F;                                 // [khalf][jl][acc][lane]
    int*   sTok  = (int*)(sredf + RED_F);
    float* sA    = (float*)(sTok + 32);

    const int w     = tid >> 5;
    const int lane  = tid & 31;
    const int jl    = w & 3;
    const int khalf = w >> 2;
    const int j     = bid * 4 + jl;

    unsigned e = g_flags[bid];   // replay-safe epoch base (owner-written)

    // ---- one-time weight preload into smem ----
    {
        const int jb = bid * 4;
        for (int i = tid; i < 12 * 192; i += NTHR) {          // Wih0: 12 rows x 768
            int row = i / 192, k4 = (i % 192) * 4;
            int g = row >> 2, jj = row & 3;
            *(float4*)&sW0[g * 3072 + jj * 768 + k4] =
                *(const float4*)(Wih0 + (size_t)(jb + jj + 512 * g) * 768 + k4);
        }
        for (int i = tid; i < 12 * 128; i += NTHR) {          // 512-wide matrices
            int row = i / 128, k4 = (i % 128) * 4;
            int g = row >> 2, jj = row & 3;
            *(float4*)&sU0[g * 2048 + jj * 512 + k4] =
                *(const float4*)(Whh0 + (size_t)(jb + jj + 512 * g) * 512 + k4);
            *(float4*)&sW1[g * 2048 + jj * 512 + k4] =
                *(const float4*)(Wih1 + (size_t)(jb + jj + 512 * g) * 512 + k4);
            *(float4*)&sU1[g * 2048 + jj * 512 + k4] =
                *(const float4*)(Whh1 + (size_t)(jb + jj + 512 * g) * 512 + k4);
        }
        for (int i = tid; i < 4 * 128; i += NTHR) {           // Wq: 4 rows x 512
            int jj = i / 128, k4 = (i % 128) * 4;
            *(float4*)&sWq[jj * 512 + k4] =
                *(const float4*)(Wq + (size_t)(jb + jj) * 512 + k4);
        }
    }

    {
        int base = bid * 128;
        if (tid < 128) {
            g_h0[0][base + tid]  = 0.f;
            g_h1[0][base + tid]  = 0.f;
            g_ctx[0][base + tid] = 0.f;
        }
    }
    gsync(++e);   // includes __syncthreads: weights visible

    for (int t = 0; t < Tn; t++) {
        const int p = t & 1;
        const float* h0p  = g_h0[p];     float* h0n  = g_h0[1 - p];
        const float* h1p  = g_h1[p];     float* h1n  = g_h1[1 - p];
        const float* ctxp = g_ctx[p];    float* ctxn = g_ctx[1 - p];

        // Phase 1: GRU0
        if (tid < Bn) sTok[tid] = tgt[tid * Tn + t];
        __syncthreads();
        {
            float4 rv[4];
            auto stage = [&](int c) {
#pragma unroll
                for (int r = 0; r < 4; r++) {
                    int idx = r * 256 + tid;
                    int b = idx >> 5, q = idx & 31;
                    const float* src;
                    if (c < 2)      src = emb + (size_t)sTok[b] * EMBn + c * 128;
                    else if (c < 6) src = ctxp + b * HIDn + (c - 2) * 128;
                    else            src = h0p + b * HIDn + (c - 6) * 128;
                    rv[r] = *(const float4*)(src + q * 4);
                }
            };
            auto sts = [&](int buf) {
#pragma unroll
                for (int r = 0; r < 4; r++) {
                    int idx = r * 256 + tid;
                    int b = idx >> 5, q = idx & 31;
                    *(float4*)&sX[buf][b][q * 4] = rv[r];
                }
            };
            unsigned long long arP = 0, azP = 0, anxP = 0, anhP = 0;
            stage(0); sts(0); __syncthreads();
            for (int c = 0; c < 10; c++) {
                if (c < 9) stage(c + 1);
                const float* sx = &sX[c & 1][lane][khalf * 64];
                if (c < 6) {
                    int col = c * 128 + khalf * 64;
                    triple16p(sx, sW0 + 0 * 3072 + jl * 768 + col,
                              sW0 + 1 * 3072 + jl * 768 + col,
                              sW0 + 2 * 3072 + jl * 768 + col, arP, azP, anxP);
                } else {
                    int col = (c - 6) * 128 + khalf * 64;
                    triple16p(sx, sU0 + 0 * 2048 + jl * 512 + col,
                              sU0 + 1 * 2048 + jl * 512 + col,
                              sU0 + 2 * 2048 + jl * 512 + col, arP, azP, anhP);
                }
                if (c < 9) sts((c + 1) & 1);
                __syncthreads();
            }
            float ar = up_sum(arP), az = up_sum(azP);
            float anx = up_sum(anxP), anh = up_sum(anhP);
            sredf[khalf * 512 + jl * 128 + 0 * 32 + lane] = ar;
            sredf[khalf * 512 + jl * 128 + 1 * 32 + lane] = az;
            sredf[khalf * 512 + jl * 128 + 2 * 32 + lane] = anx;
            sredf[khalf * 512 + jl * 128 + 3 * 32 + lane] = anh;
            __syncthreads();
            if (khalf == 0) {
                ar  += sredf[512 + jl * 128 + 0 * 32 + lane];
                az  += sredf[512 + jl * 128 + 1 * 32 + lane];
                anx += sredf[512 + jl * 128 + 2 * 32 + lane];
                anh += sredf[512 + jl * 128 + 3 * 32 + lane];
                float r = 1.f / (1.f + expf(-(ar + bih0[j] + bhh0[j])));
                float z = 1.f / (1.f + expf(-(az + bih0[j + 512] + bhh0[j + 512])));
                float n = tanhf(anx + bih0[j + 1024] + r * (anh + bhh0[j + 1024]));
                float hp = h0p[lane * HIDn + j];
                h0n[lane * HIDn + j] = (1.f - z) * n + z * hp;
            }
        }
        gsync(++e);

        // Phase 2: GRU1
        {
            float4 rv[4];
            auto stage = [&](int c) {
#pragma unroll
                for (int r = 0; r < 4; r++) {
                    int idx = r * 256 + tid;
                    int b = idx >> 5, q = idx & 31;
                    const float* src = (c < 4) ? (h0n + b * HIDn + c * 128)
                                               : (h1p + b * HIDn + (c - 4) * 128);
                    rv[r] = *(const float4*)(src + q * 4);
                }
            };
            auto sts = [&](int buf) {
#pragma unroll
                for (int r = 0; r < 4; r++) {
                    int idx = r * 256 + tid;
                    int b = idx >> 5, q = idx & 31;
                    *(float4*)&sX[buf][b][q * 4] = rv[r];
                }
            };
            unsigned long long arP = 0, azP = 0, anxP = 0, anhP = 0;
            stage(0); sts(0); __syncthreads();
            for (int c = 0; c < 8; c++) {
                if (c < 7) stage(c + 1);
                const float* sx = &sX[c & 1][lane][khalf * 64];
                if (c < 4) {
                    int col = c * 128 + khalf * 64;
                    triple16p(sx, sW1 + 0 * 2048 + jl * 512 + col,
                              sW1 + 1 * 2048 + jl * 512 + col,
                              sW1 + 2 * 2048 + jl * 512 + col, arP, azP, anxP);
                } else {
                    int col = (c - 4) * 128 + khalf * 64;
                    triple16p(sx, sU1 + 0 * 2048 + jl * 512 + col,
                              sU1 + 1 * 2048 + jl * 512 + col,
                              sU1 + 2 * 2048 + jl * 512 + col, arP, azP, anhP);
                }
                if (c < 7) sts((c + 1) & 1);
                __syncthreads();
            }
            float ar = up_sum(arP), az = up_sum(azP);
            float anx = up_sum(anxP), anh = up_sum(anhP);
            sredf[khalf * 512 + jl * 128 + 0 * 32 + lane] = ar;
            sredf[khalf * 512 + jl * 128 + 1 * 32 + lane] = az;
            sredf[khalf * 512 + jl * 128 + 2 * 32 + lane] = anx;
            sredf[khalf * 512 + jl * 128 + 3 * 32 + lane] = anh;
            __syncthreads();
            if (khalf == 0) {
                ar  += sredf[512 + jl * 128 + 0 * 32 + lane];
                az  += sredf[512 + jl * 128 + 1 * 32 + lane];
                anx += sredf[512 + jl * 128 + 2 * 32 + lane];
                anh += sredf[512 + jl * 128 + 3 * 32 + lane];
                float r = 1.f / (1.f + expf(-(ar + bih1[j] + bhh1[j])));
                float z = 1.f / (1.f + expf(-(az + bih1[j + 512] + bhh1[j + 512])));
                float n = tanhf(anx + bih1[j + 1024] + r * (anh + bhh1[j + 1024]));
                float hp = h1p[lane * HIDn + j];
                float hnew = (1.f - z) * n + z * hp;
                h1n[lane * HIDn + j] = hnew;
                g_dc[((size_t)lane * Tn + t) * (2 * HIDn) + j] = hnew;
            }
        }
        gsync(++e);

        // Phase 3: q = dec @ Wq^T
        {
            float4 rv[4];
            auto stage = [&](int c) {
#pragma unroll
                for (int r = 0; r < 4; r++) {
                    int idx = r * 256 + tid;
                    int b = idx >> 5, q = idx & 31;
                    rv[r] = *(const float4*)(h1n + b * HIDn + c * 128 + q * 4);
                }
            };
            auto sts = [&](int buf) {
#pragma unroll
                for (int r = 0; r < 4; r++) {
                    int idx = r * 256 + tid;
                    int b = idx >> 5, q = idx & 31;
                    *(float4*)&sX[buf][b][q * 4] = rv[r];
                }
            };
            unsigned long long aqP = 0;
            stage(0); sts(0); __syncthreads();
            for (int c = 0; c < 4; c++) {
                if (c < 3) stage(c + 1);
                const float* sx = &sX[c & 1][lane][khalf * 64];
                single16p(sx, sWq + jl * 512 + c * 128 + khalf * 64, aqP);
                if (c < 3) sts((c + 1) & 1);
                __syncthreads();
            }
            float aq = up_sum(aqP);
            sredf[khalf * 512 + jl * 128 + lane] = aq;
            __syncthreads();
            if (khalf == 0) {
                aq += sredf[512 + jl * 128 + lane];
                g_q[lane * HIDn + j] = aq;
            }
        }
        gsync(++e);

        // Phase 4: scores (HW tanh)
        {
#pragma unroll
            for (int r = 0; r < 2; r++) {
                int pi = bid * 16 + w * 2 + r;
                int b = pi >> 6, s = pi & 63;
                const float* qb = g_q + b * HIDn;
                const float* kp = g_kproj + ((size_t)b * Sn + s) * HIDn;
                float acc = 0.f;
#pragma unroll
                for (int i = 0; i < 16; i++) {
                    int h = lane + i * 32;
                    acc = fmaf(vvec[h], tanh_fast(qb[h] + kp[h]), acc);
                }
#pragma unroll
                for (int o = 16; o; o >>= 1) acc += __shfl_xor_sync(0xFFFFFFFFu, acc, o);
                if (lane == 0) g_e[b * Sn + s] = mask[b * Sn + s] ? -1e9f : acc;
            }
        }
        gsync(++e);

        // Phase 5: softmax + ctx (packed over h pairs; per-h order unchanged)
        {
            const int b  = bid >> 2;
            const int hs = (bid & 3) * 128;
            if (w == 0) {
                float e0 = g_e[b * Sn + lane];
                float e1 = g_e[b * Sn + 32 + lane];
                float m = fmaxf(e0, e1);
#pragma unroll
                for (int o = 16; o; o >>= 1) m = fmaxf(m, __shfl_xor_sync(0xFFFFFFFFu, m, o));
                float x0 = expf(e0 - m), x1 = expf(e1 - m);
                float ssum = x0 + x1;
#pragma unroll
                for (int o = 16; o; o >>= 1) ssum += __shfl_xor_sync(0xFFFFFFFFu, ssum, o);
                float rinv = 1.f / ssum;
                sA[lane]      = x0 * rinv;
                sA[lane + 32] = x1 * rinv;
            }
            __syncthreads();
            if (tid < 64) {
                int h = hs + tid * 2;
                const float* eb = enc + (size_t)b * Sn * HIDn + h;
                unsigned long long c2 = 0;
#pragma unroll 8
                for (int s = 0; s < Sn; s++)
                    fma2(c2, dup2(sA[s]), *(const unsigned long long*)(eb + (size_t)s * HIDn));
                unsigned clo, chi;
                asm("mov.b64 {%0, %1}, %2;" : "=r"(clo), "=r"(chi) : "l"(c2));
                float2 cv = make_float2(__uint_as_float(clo), __uint_as_float(chi));
                *(float2*)(ctxn + b * HIDn + h) = cv;
                *(float2*)(g_dc + ((size_t)b * Tn + t) * (2 * HIDn) + HIDn + h) = cv;
            }
        }
        gsync(++e);
    }
}

// ---------------- small fp32 GEMM for kproj ----------------
#define GBM 64
#define GBN 64
#define GBK 16
__global__ __launch_bounds__(256) void gemm_abt_kernel(
    const float* __restrict__ A, const float* __restrict__ B,
    float* __restrict__ C, int M, int N, int K)
{
    __shared__ __align__(16) float As[GBK][GBM + 4];
    __shared__ __align__(16) float Bs[GBK][GBN + 4];
    const int tid = threadIdx.x;
    const int rowBase = blockIdx.y * GBM;
    const int colBase = blockIdx.x * GBN;
    const int tm = tid >> 4;
    const int tn = tid & 15;
    const int lr  = tid >> 2;
    const int lk4 = (tid & 3) * 4;

    float acc[4][4];
#pragma unroll
    for (int i = 0; i < 4; i++)
#pragma unroll
        for (int jj = 0; jj < 4; jj++) acc[i][jj] = 0.f;

    const float* Aptr = A + (size_t)(rowBase + lr) * K + lk4;
    const float* Bptr = B + (size_t)(colBase + lr) * K + lk4;
    for (int kt = 0; kt < K; kt += GBK) {
        float4 a4 = *(const float4*)(Aptr + kt);
        float4 b4 = *(const float4*)(Bptr + kt);
        As[lk4 + 0][lr] = a4.x; As[lk4 + 1][lr] = a4.y;
        As[lk4 + 2][lr] = a4.z; As[lk4 + 3][lr] = a4.w;
        Bs[lk4 + 0][lr] = b4.x; Bs[lk4 + 1][lr] = b4.y;
        Bs[lk4 + 2][lr] = b4.z; Bs[lk4 + 3][lr] = b4.w;
        __syncthreads();
#pragma unroll
        for (int kk = 0; kk < GBK; kk++) {
            float4 av = *(const float4*)(&As[kk][tm * 4]);
            float4 bv = *(const float4*)(&Bs[kk][tn * 4]);
            float ar[4] = {av.x, av.y, av.z, av.w};
            float br[4] = {bv.x, bv.y, bv.z, bv.w};
#pragma unroll
            for (int i = 0; i < 4; i++)
#pragma unroll
                for (int jj = 0; jj < 4; jj++)
                    acc[i][jj] = fmaf(ar[i], br[jj], acc[i][jj]);
        }
        __syncthreads();
    }
#pragma unroll
    for (int i = 0; i < 4; i++) {
        float4 o;
        o.x = acc[i][0]; o.y = acc[i][1]; o.z = acc[i][2]; o.w = acc[i][3];
        *(float4*)(C + (size_t)(rowBase + tm * 4 + i) * N + colBase + tn * 4) = o;
    }
}

// ---------------- launch ----------------
extern "C" void kernel_launch(void* const* d_in, const int* in_sizes, int n_in,
                              void* d_out, int out_size)
{
    const float*         enc       = (const float*)d_in[0];
    const unsigned char* src_mask  = (const unsigned char*)d_in[1];
    const int*           tgt_in    = (const int*)d_in[2];
    const float*         emb_table = (const float*)d_in[3];
    const float*         W_ih0     = (const float*)d_in[4];
    const float*         W_hh0     = (const float*)d_in[5];
    const float*         b_ih0     = (const float*)d_in[6];
    const float*         b_hh0     = (const float*)d_in[7];
    const float*         W_ih1     = (const float*)d_in[8];
    const float*         W_hh1     = (const float*)d_in[9];
    const float*         b_ih1     = (const float*)d_in[10];
    const float*         b_hh1     = (const float*)d_in[11];
    const float*         Wq        = (const float*)d_in[12];
    const float*         Wk        = (const float*)d_in[13];
    const float*         vvec      = (const float*)d_in[14];
    const float*         W_out     = (const float*)d_in[15];
    const float*         b_out     = (const float*)d_in[16];
    float*               out       = (float*)d_out;

    float* kproj_ptr = nullptr;
    float* dc_ptr    = nullptr;
    __half *ah_p = nullptr;
    cudaGetSymbolAddress((void**)&kproj_ptr, g_kproj);
    cudaGetSymbolAddress((void**)&dc_ptr, g_dc);
    cudaGetSymbolAddress((void**)&ah_p, g_ah);

    const int smem_bytes = 2 * STGB;   // 65536
    cudaFuncSetAttribute(hmma_gemm_vocab,
                         cudaFuncAttributeMaxDynamicSharedMemorySize, smem_bytes);
    cudaFuncSetAttribute(decoder_persistent,
                         cudaFuncAttributeMaxDynamicSharedMemorySize, DEC_SMEM_B);

    // k_proj = enc_out @ Wk^T
    {
        dim3 grid(HIDn / GBN, (Bn * Sn) / GBM);
        gemm_abt_kernel<<<grid, 256>>>(enc, Wk, kproj_ptr, Bn * Sn, HIDn, HIDn);
    }

    // full recurrence (smem-resident weights, packed f32x2 FMA) + W-split spares
    decoder_persistent<<<NBLK + EXTRA, NTHR, DEC_SMEM_B>>>(
        enc, src_mask, tgt_in, emb_table,
        W_ih0, W_hh0, b_ih0, b_hh0,
        W_ih1, W_hh1, b_ih1, b_hh1,
        Wq, vvec, W_out);

    // split dc -> tiled/swizzled fp16 (hi only)
    {
        int nchunks = Bn * Tn * (KV / 8);
        split_h_kernel<<<(nchunks + 255) / 256, 256>>>(dc_ptr, ah_p, nchunks);
    }

    // logits via fp16 1-term HMMA GEMM
    {
        dim3 grid((Bn * Tn) / 128, VOCn / 128);
        hmma_gemm_vocab<<<grid, 256, smem_bytes>>>(b_out, out);
    }
}

// round 15
// speedup vs baseline: 1.0507x; 1.0507x over previous
#include <cuda_runtime.h>
#include <cuda_fp16.h>
#include <math.h>
#include <stdint.h>

#define Bn   32
#define Sn   64
#define Tn   64
#define EMBn 256
#define HIDn 512
#define VOCn 32000
#define KV   1024      // 2*HID

#define NBLK  128      // barrier participants
#define EXTRA 20       // spare blocks doing W-split
#define NTHR  256

// vocab GEMM tiling
#define BKv   64
#define NKC   (KV / BKv)              // 16 k-chunks
#define BLKB  (128 * BKv * 2)         // 16384 bytes per 128x64 fp16 tile block
#define STGB  (2 * BLKB)              // 32768 bytes per stage (Ah, Wh)

// dynamic smem for decoder (floats): 3 x 4096 chunk ring + weights + red + sA
#define DEC_SMEM_F (12288 + 9216 + 6144 + 6144 + 6144 + 2048 + 1024 + 64)
#define DEC_SMEM_B (DEC_SMEM_F * 4)   // 172288 bytes

// ---------------- scratch state (device globals; no allocation) ----------------
__device__ __align__(16) float g_kproj[Bn * Sn * HIDn];
// transposed state: element (k, b) at (k>>2)*128 + b*4 + (k&3)
__device__ __align__(1024) float g_h0T[2][HIDn * Bn];
__device__ __align__(1024) float g_h1T[2][HIDn * Bn];
__device__ __align__(1024) float g_ctxT[2][HIDn * Bn];
__device__ __align__(1024) float g_embT[Tn * EMBn * Bn];   // [t][kg][b][4], 2 MB
__device__ __align__(16) float g_q[Bn * HIDn];
__device__ __align__(16) float g_e[Bn * Sn];
__device__ __align__(16) float g_dc[Bn * Tn * 2 * HIDn];

// tiled+swizzled fp16 panels for the vocab GEMM
__device__ __align__(1024) __half g_wh[(size_t)VOCn * KV];
__device__ __align__(1024) __half g_ah[Bn * Tn * KV];

// contention-free barrier state
__device__ volatile unsigned g_flags[NBLK];
__device__ volatile unsigned g_rel;

// ================= helpers =================
__device__ __forceinline__ uint32_t smem_u32(const void* p) {
    uint32_t a;
    asm("{ .reg .u64 t; cvta.to.shared.u64 t, %1; cvt.u32.u64 %0, t; }" : "=r"(a) : "l"(p));
    return a;
}

#define MBAR_INIT(addr, cnt) \
    asm volatile("mbarrier.init.shared.b64 [%0], %1;" :: "r"(addr), "r"(cnt) : "memory")
#define MBAR_EXPECT_TX(addr, bytes) \
    asm volatile("mbarrier.arrive.expect_tx.shared.b64 _, [%0], %1;" :: "r"(addr), "r"(bytes) : "memory")
#define MBAR_WAIT(addr, parity) do {                                            \
    uint32_t _m = (addr), _p = (parity), _d;                                    \
    asm volatile("{\n\t.reg .pred p;\n\t"                                       \
        "mbarrier.try_wait.parity.acquire.cta.shared::cta.b64 p, [%1], %2;\n\t" \
        "selp.b32 %0, 1, 0, p;\n\t}" : "=r"(_d) : "r"(_m), "r"(_p) : "memory"); \
    if (!_d) {                                                                  \
        asm volatile("{\n\t.reg .pred P1;\n\tWL_%=:\n\t"                        \
            "mbarrier.try_wait.parity.acquire.cta.shared::cta.b64 P1, [%0], %1, 0x989680;\n\t" \
            "@P1 bra.uni WD_%=;\n\tbra.uni WL_%=;\n\tWD_%=:\n\t}"               \
            :: "r"(_m), "r"(_p) : "memory");                                    \
    } } while (0)

__device__ __forceinline__ void bulk_g2s(uint32_t dst, const void* src,
                                         uint32_t bytes, uint32_t bar) {
    asm volatile(
        "cp.async.bulk.shared::cluster.global.mbarrier::complete_tx::bytes "
        "[%0], [%1], %2, [%3];"
        :: "r"(dst), "l"(src), "r"(bytes), "r"(bar) : "memory");
}

__device__ __forceinline__ void ldm4(uint32_t& r0, uint32_t& r1, uint32_t& r2,
                                     uint32_t& r3, uint32_t a) {
    asm volatile("ldmatrix.sync.aligned.m8n8.x4.shared.b16 {%0,%1,%2,%3}, [%4];"
                 : "=r"(r0), "=r"(r1), "=r"(r2), "=r"(r3) : "r"(a));
}

__device__ __forceinline__ void mma_f16(float* c, const uint32_t* a,
                                        uint32_t b0, uint32_t b1) {
    asm volatile(
        "mma.sync.aligned.m16n8k16.row.col.f32.f16.f16.f32 "
        "{%0,%1,%2,%3}, {%4,%5,%6,%7}, {%8,%9}, {%0,%1,%2,%3};"
        : "+f"(c[0]), "+f"(c[1]), "+f"(c[2]), "+f"(c[3])
        : "r"(a[0]), "r"(a[1]), "r"(a[2]), "r"(a[3]), "r"(b0), "r"(b1));
}

__device__ __forceinline__ float tanh_fast(float x) {
    float y;
    asm("tanh.approx.f32 %0, %1;" : "=f"(y) : "f"(x));
    return y;
}

// swizzle within a 16KB GEMM tile block
__device__ __forceinline__ uint32_t swz(uint32_t off) {
    return off ^ (((off >> 7) & 7u) << 4);
}

// ================= split fp32 -> fp16 hi, tiled + swizzled (A panels) =========
__global__ __launch_bounds__(256) void split_h_kernel(
    const float* __restrict__ src, __half* __restrict__ hi, int nchunks)
{
    int id = blockIdx.x * 256 + threadIdx.x;
    if (id >= nchunks) return;
    int n  = id >> 7;
    int k0 = (id & 127) * 8;
    const float* s = src + (size_t)n * KV + k0;
    float4 x0 = *(const float4*)s;
    float4 x1 = *(const float4*)(s + 4);
    float xs[8] = {x0.x, x0.y, x0.z, x0.w, x1.x, x1.y, x1.z, x1.w};

    uint32_t hw[4];
#pragma unroll
    for (int i = 0; i < 4; i++) {
        __half2 hp = __halves2half2(__float2half_rn(xs[2 * i]),
                                    __float2half_rn(xs[2 * i + 1]));
        hw[i] = *(uint32_t*)&hp;
    }

    int nt = n >> 7, r = n & 127, kc = k0 >> 6;
    uint32_t off = swz((uint32_t)(r * 128 + (k0 & 63) * 2));
    size_t blk = ((size_t)nt * NKC + kc) * BLKB;
    *(uint4*)((char*)hi + blk + off) = make_uint4(hw[0], hw[1], hw[2], hw[3]);
}

// ================= HMMA fp16 1-term vocab GEMM (TMA-bulk, 2-stage) ============
__global__ __launch_bounds__(256) void hmma_gemm_vocab(
    const float* __restrict__ bias, float* __restrict__ C)
{
    extern __shared__ __align__(128) char sm[];
    __shared__ __align__(8) uint64_t mbar[2];
    __shared__ float sBias[128];

    const int tid  = threadIdx.x;
    const int wid  = tid >> 5;
    const int lane = tid & 31;
    const int m_t = blockIdx.x, n_t = blockIdx.y;
    const int m0 = m_t * 128,   n0 = n_t * 128;
    const int warp_m = wid & 1;
    const int warp_n = wid >> 1;

    if (tid < 128) sBias[tid] = bias[n0 + tid];

    const uint32_t smb = smem_u32(sm);
    const uint32_t mb  = smem_u32(mbar);

    const char* gA = (const char*)g_ah + (size_t)m_t * NKC * BLKB;
    const char* gH = (const char*)g_wh + (size_t)n_t * NKC * BLKB;

    if (tid == 0) { MBAR_INIT(mb, 1); MBAR_INIT(mb + 8, 1); }
    __syncthreads();

    auto issue = [&](int s, int buf) {
        uint32_t d   = smb + buf * STGB;
        uint32_t bar = mb + buf * 8;
        MBAR_EXPECT_TX(bar, (uint32_t)STGB);
        bulk_g2s(d,        gA + (size_t)s * BLKB, BLKB, bar);
        bulk_g2s(d + BLKB, gH + (size_t)s * BLKB, BLKB, bar);
    };
    if (tid == 0) issue(0, 0);

    float acc[4][4][4];
#pragma unroll
    for (int mt = 0; mt < 4; mt++)
#pragma unroll
        for (int nt = 0; nt < 4; nt++)
#pragma unroll
            for (int r = 0; r < 4; r++) acc[mt][nt][r] = 0.f;

    const int a_row = warp_m * 64 + (lane & 15);
    const int a_cb  = (lane >> 4) * 16;
    const int b_row = warp_n * 32 + ((lane >> 4) << 3) + (lane & 7);
    const int b_cb  = ((lane >> 3) & 1) * 16;

    for (int s = 0; s < NKC; s++) {
        const int buf = s & 1;
        MBAR_WAIT(mb + buf * 8, (uint32_t)((s >> 1) & 1));
        if (tid == 0 && s + 1 < NKC) issue(s + 1, buf ^ 1);

        const uint32_t sA  = smb + buf * STGB;
        const uint32_t sWh = sA + BLKB;

#pragma unroll
        for (int koff = 0; koff < BKv; koff += 16) {
            uint32_t ah[4][4], bh[2][4];
#pragma unroll
            for (int mt = 0; mt < 4; mt++) {
                uint32_t off = swz((uint32_t)((a_row + mt * 16) * 128 +
                                              a_cb + koff * 2));
                ldm4(ah[mt][0], ah[mt][1], ah[mt][2], ah[mt][3], sA + off);
            }
#pragma unroll
            for (int p = 0; p < 2; p++) {
                uint32_t off = swz((uint32_t)((b_row + p * 16) * 128 +
                                              b_cb + koff * 2));
                ldm4(bh[p][0], bh[p][1], bh[p][2], bh[p][3], sWh + off);
            }
#pragma unroll
            for (int mt = 0; mt < 4; mt++) {
#pragma unroll
                for (int nt = 0; nt < 4; nt++) {
                    int p = nt >> 1, h = (nt & 1) * 2;
                    mma_f16(acc[mt][nt], ah[mt], bh[p][h], bh[p][h + 1]);
                }
            }
        }
        __syncthreads();
    }

    const int er = (lane >> 2);
    const int ec = (lane & 3) * 2;
#pragma unroll
    for (int mt = 0; mt < 4; mt++) {
#pragma unroll
        for (int nt = 0; nt < 4; nt++) {
            int row  = m0 + warp_m * 64 + mt * 16 + er;
            int colL = warp_n * 32 + nt * 8 + ec;
            int col  = n0 + colL;
            float2 o0, o1;
            o0.x = acc[mt][nt][0] + sBias[colL];
            o0.y = acc[mt][nt][1] + sBias[colL + 1];
            o1.x = acc[mt][nt][2] + sBias[colL];
            o1.y = acc[mt][nt][3] + sBias[colL + 1];
            *(float2*)(C + (size_t)row * VOCn + col)       = o0;
            *(float2*)(C + (size_t)(row + 8) * VOCn + col) = o1;
        }
    }
}

// ---------------- contention-free grid barrier ----------------
__device__ __forceinline__ void gsync(unsigned e) {
    __syncthreads();
    const int tid = threadIdx.x;
    const int bid = blockIdx.x;
    if (tid == 0) {
        asm volatile("fence.proxy.async;" ::: "memory");
        __threadfence();
        g_flags[bid] = e;
    }
    if (bid == 0) {
        if (tid < NBLK) { while (g_flags[tid] != e) { } }
        __syncthreads();
        if (tid == 0) { __threadfence(); g_rel = e; }
    } else {
        if (tid == 0) { while (g_rel != e) { } __threadfence(); }
    }
    __syncthreads();
}

// ---------------- dot helpers (transposed-chunk x: stride 128 floats) ---------
__device__ __forceinline__ void triple16T(const float* __restrict__ sx,
    const float* __restrict__ w0, const float* __restrict__ w1,
    const float* __restrict__ w2, float& a0, float& a1, float& a2)
{
#pragma unroll
    for (int i = 0; i < 16; i++) {
        float4 x = *(const float4*)(sx + i * 128);
        float4 u = *(const float4*)(w0 + i * 4);
        float4 v = *(const float4*)(w1 + i * 4);
        float4 s = *(const float4*)(w2 + i * 4);
        a0 = fmaf(x.x, u.x, fmaf(x.y, u.y, fmaf(x.z, u.z, fmaf(x.w, u.w, a0))));
        a1 = fmaf(x.x, v.x, fmaf(x.y, v.y, fmaf(x.z, v.z, fmaf(x.w, v.w, a1))));
        a2 = fmaf(x.x, s.x, fmaf(x.y, s.y, fmaf(x.z, s.z, fmaf(x.w, s.w, a2))));
    }
}
__device__ __forceinline__ void single16T(const float* __restrict__ sx,
    const float* __restrict__ w0, float& a0)
{
#pragma unroll
    for (int i = 0; i < 16; i++) {
        float4 x = *(const float4*)(sx + i * 128);
        float4 u = *(const float4*)(w0 + i * 4);
        a0 = fmaf(x.x, u.x, fmaf(x.y, u.y, fmaf(x.z, u.z, fmaf(x.w, u.w, a0))));
    }
}

// ---------------- persistent recurrence kernel (+W-split on spare blocks) -----
// 256 threads: 8 warps = 4 j (jl) x 2 k-halves (khalf). lane = batch.
// Weights in SMEM; activation chunks TMA-bulk staged via 3-buffer ring.
__global__ __launch_bounds__(NTHR, 1) void decoder_persistent(
    const float* __restrict__ enc, const unsigned char* __restrict__ mask,
    const int* __restrict__ tgt, const float* __restrict__ emb,
    const float* __restrict__ Wih0, const float* __restrict__ Whh0,
    const float* __restrict__ bih0, const float* __restrict__ bhh0,
    const float* __restrict__ Wih1, const float* __restrict__ Whh1,
    const float* __restrict__ bih1, const float* __restrict__ bhh1,
    const float* __restrict__ Wq, const float* __restrict__ vvec,
    const float* __restrict__ Wout)
{
    const int tid = threadIdx.x;
    const int bid = blockIdx.x;

    // ===== spare blocks: stream W_out -> fp16 tiled/swizzled panels =====
    if (bid >= NBLK) {
        const int sp  = bid - NBLK;
        const int nch = VOCn * (KV / 8);
        for (int id = sp * NTHR + tid; id < nch; id += EXTRA * NTHR) {
            int n  = id >> 7;
            int k0 = (id & 127) * 8;
            const float* s = Wout + (size_t)n * KV + k0;
            float4 x0 = __ldcs((const float4*)s);
            float4 x1 = __ldcs((const float4*)(s + 4));
            float xs[8] = {x0.x, x0.y, x0.z, x0.w, x1.x, x1.y, x1.z, x1.w};
            uint32_t hw[4];
#pragma unroll
            for (int i = 0; i < 4; i++) {
                __half2 hp = __halves2half2(__float2half_rn(xs[2 * i]),
                                            __float2half_rn(xs[2 * i + 1]));
                hw[i] = *(uint32_t*)&hp;
            }
            int nt = n >> 7, r = n & 127, kc = k0 >> 6;
            uint32_t off = swz((uint32_t)(r * 128 + (k0 & 63) * 2));
            size_t blk = ((size_t)nt * NKC + kc) * BLKB;
            float4 ov = make_float4(__uint_as_float(hw[0]), __uint_as_float(hw[1]),
                                    __uint_as_float(hw[2]), __uint_as_float(hw[3]));
            __stcs((float4*)((char*)g_wh + blk + off), ov);
        }
        return;
    }

    // ===== barrier-participating blocks =====
    extern __shared__ __align__(16) float dsm[];
    float* sXT   = dsm;                       // 3 x 4096 (chunk ring)
    float* sW0   = dsm + 12288;               // [g][jl][768]
    float* sU0   = sW0 + 9216;                // [g][jl][512]
    float* sW1   = sU0 + 6144;
    float* sU1   = sW1 + 6144;
    float* sWq   = sU1 + 6144;                // [jl][512]
    float* sredf = sWq + 2048;                // 1024
    float* sA    = sredf + 1024;              // 64
    __shared__ __align__(8) uint64_t mbar[3];

    const int w     = tid >> 5;
    const int lane  = tid & 31;
    const int jl    = w & 3;
    const int khalf = w >> 2;
    const int j     = bid * 4 + jl;

    const uint32_t sxa = smem_u32(dsm);
    const uint32_t mb  = smem_u32(mbar);

    unsigned e = g_flags[bid];   // replay-safe epoch base

    if (tid == 0) { MBAR_INIT(mb, 1); MBAR_INIT(mb + 8, 1); MBAR_INIT(mb + 16, 1); }

    // ---- one-time weight preload into smem ----
    {
        const int jb = bid * 4;
        for (int i = tid; i < 12 * 192; i += NTHR) {
            int row = i / 192, k4 = (i % 192) * 4;
            int g = row >> 2, jj = row & 3;
            *(float4*)&sW0[g * 3072 + jj * 768 + k4] =
                *(const float4*)(Wih0 + (size_t)(jb + jj + 512 * g) * 768 + k4);
        }
        for (int i = tid; i < 12 * 128; i += NTHR) {
            int row = i / 128, k4 = (i % 128) * 4;
            int g = row >> 2, jj = row & 3;
            *(float4*)&sU0[g * 2048 + jj * 512 + k4] =
                *(const float4*)(Whh0 + (size_t)(jb + jj + 512 * g) * 512 + k4);
            *(float4*)&sW1[g * 2048 + jj * 512 + k4] =
                *(const float4*)(Wih1 + (size_t)(jb + jj + 512 * g) * 512 + k4);
            *(float4*)&sU1[g * 2048 + jj * 512 + k4] =
                *(const float4*)(Whh1 + (size_t)(jb + jj + 512 * g) * 512 + k4);
        }
        for (int i = tid; i < 4 * 128; i += NTHR) {
            int jj = i / 128, k4 = (i % 128) * 4;
            *(float4*)&sWq[jj * 512 + k4] =
                *(const float4*)(Wq + (size_t)(jb + jj) * 512 + k4);
        }
    }

    // ---- one-time transposed embedding gather: g_embT[t][kg][b][4] ----
    for (int i = bid * NTHR + tid; i < Tn * 64 * Bn; i += NBLK * NTHR) {
        int t0 = i >> 11;
        int kg = (i >> 5) & 63;
        int b  = i & 31;
        int tok = tgt[b * Tn + t0];
        float4 v = *(const float4*)(emb + (size_t)tok * EMBn + kg * 4);
        *(float4*)&g_embT[(size_t)t0 * 8192 + kg * 128 + b * 4] = v;
    }

    {
        if (tid < 128) {
            g_h0T[0][bid * 128 + tid]  = 0.f;
            g_h1T[0][bid * 128 + tid]  = 0.f;
            g_ctxT[0][bid * 128 + tid] = 0.f;
        }
    }
    gsync(++e);   // mbar init + weights + embT + zeros all visible

    int G = 0;    // global chunk counter: buf = G%3, parity = (G/3)&1

    auto issue = [&](int gi, const float* src) {
        int buf = gi % 3;
        MBAR_EXPECT_TX(mb + buf * 8, 16384u);
        bulk_g2s(sxa + buf * 16384, src, 16384u, mb + buf * 8);
    };

    for (int t = 0; t < Tn; t++) {
        const int p = t & 1;
        const float* h0pT  = g_h0T[p];     float* h0nT  = g_h0T[1 - p];
        const float* h1pT  = g_h1T[p];     float* h1nT  = g_h1T[1 - p];
        const float* ctxpT = g_ctxT[p];    float* ctxnT = g_ctxT[1 - p];

        // ===== Phase 1: GRU0 (10 chunks) =====
        {
            auto p1src = [&](int c) -> const float* {
                if (c < 2) return g_embT + (size_t)t * 8192 + c * 4096;
                if (c < 6) return ctxpT + (c - 2) * 4096;
                return h0pT + (c - 6) * 4096;
            };
            if (tid == 0) { issue(G, p1src(0)); issue(G + 1, p1src(1)); issue(G + 2, p1src(2)); }
            float ar = 0.f, az = 0.f, anx = 0.f, anh = 0.f;
            for (int c = 0; c < 10; c++) {
                int g = G + c, buf = g % 3;
                MBAR_WAIT(mb + buf * 8, (uint32_t)((g / 3) & 1));
                const float* sx = sXT + buf * 4096 + (khalf * 16) * 128 + lane * 4;
                if (c < 6) {
                    int col = c * 128 + khalf * 64;
                    triple16T(sx, sW0 + 0 * 3072 + jl * 768 + col,
                              sW0 + 1 * 3072 + jl * 768 + col,
                              sW0 + 2 * 3072 + jl * 768 + col, ar, az, anx);
                } else {
                    int col = (c - 6) * 128 + khalf * 64;
                    triple16T(sx, sU0 + 0 * 2048 + jl * 512 + col,
                              sU0 + 1 * 2048 + jl * 512 + col,
                              sU0 + 2 * 2048 + jl * 512 + col, ar, az, anh);
                }
                __syncthreads();
                if (tid == 0 && c + 3 < 10) issue(G + c + 3, p1src(c + 3));
            }
            G += 10;
            sredf[khalf * 512 + jl * 128 + 0 * 32 + lane] = ar;
            sredf[khalf * 512 + jl * 128 + 1 * 32 + lane] = az;
            sredf[khalf * 512 + jl * 128 + 2 * 32 + lane] = anx;
            sredf[khalf * 512 + jl * 128 + 3 * 32 + lane] = anh;
            __syncthreads();
            if (khalf == 0) {
                ar  += sredf[512 + jl * 128 + 0 * 32 + lane];
                az  += sredf[512 + jl * 128 + 1 * 32 + lane];
                anx += sredf[512 + jl * 128 + 2 * 32 + lane];
                anh += sredf[512 + jl * 128 + 3 * 32 + lane];
                float r = 1.f / (1.f + expf(-(ar + bih0[j] + bhh0[j])));
                float z = 1.f / (1.f + expf(-(az + bih0[j + 512] + bhh0[j + 512])));
                float n = tanhf(anx + bih0[j + 1024] + r * (anh + bhh0[j + 1024]));
                float hp = h0pT[bid * 128 + lane * 4 + jl];
                h0nT[bid * 128 + lane * 4 + jl] = (1.f - z) * n + z * hp;
            }
        }
        gsync(++e);

        // ===== Phase 2: GRU1 (8 chunks) =====
        {
            auto p2src = [&](int c) -> const float* {
                return (c < 4) ? (h0nT + c * 4096) : (h1pT + (c - 4) * 4096);
            };
            if (tid == 0) { issue(G, p2src(0)); issue(G + 1, p2src(1)); issue(G + 2, p2src(2)); }
            float ar = 0.f, az = 0.f, anx = 0.f, anh = 0.f;
            for (int c = 0; c < 8; c++) {
                int g = G + c, buf = g % 3;
                MBAR_WAIT(mb + buf * 8, (uint32_t)((g / 3) & 1));
                const float* sx = sXT + buf * 4096 + (khalf * 16) * 128 + lane * 4;
                if (c < 4) {
                    int col = c * 128 + khalf * 64;
                    triple16T(sx, sW1 + 0 * 2048 + jl * 512 + col,
                              sW1 + 1 * 2048 + jl * 512 + col,
                              sW1 + 2 * 2048 + jl * 512 + col, ar, az, anx);
                } else {
                    int col = (c - 4) * 128 + khalf * 64;
                    triple16T(sx, sU1 + 0 * 2048 + jl * 512 + col,
                              sU1 + 1 * 2048 + jl * 512 + col,
                              sU1 + 2 * 2048 + jl * 512 + col, ar, az, anh);
                }
                __syncthreads();
                if (tid == 0 && c + 3 < 8) issue(G + c + 3, p2src(c + 3));
            }
            G += 8;
            sredf[khalf * 512 + jl * 128 + 0 * 32 + lane] = ar;
            sredf[khalf * 512 + jl * 128 + 1 * 32 + lane] = az;
            sredf[khalf * 512 + jl * 128 + 2 * 32 + lane] = anx;
            sredf[khalf * 512 + jl * 128 + 3 * 32 + lane] = anh;
            __syncthreads();
            if (khalf == 0) {
                ar  += sredf[512 + jl * 128 + 0 * 32 + lane];
                az  += sredf[512 + jl * 128 + 1 * 32 + lane];
                anx += sredf[512 + jl * 128 + 2 * 32 + lane];
                anh += sredf[512 + jl * 128 + 3 * 32 + lane];
                float r = 1.f / (1.f + expf(-(ar + bih1[j] + bhh1[j])));
                float z = 1.f / (1.f + expf(-(az + bih1[j + 512] + bhh1[j + 512])));
                float n = tanhf(anx + bih1[j + 1024] + r * (anh + bhh1[j + 1024]));
                float hp = h1pT[bid * 128 + lane * 4 + jl];
                float hnew = (1.f - z) * n + z * hp;
                h1nT[bid * 128 + lane * 4 + jl] = hnew;
                g_dc[((size_t)lane * Tn + t) * (2 * HIDn) + j] = hnew;
            }
        }
        gsync(++e);

        // ===== Phase 3: q = dec @ Wq^T (4 chunks) =====
        {
            if (tid == 0) {
                issue(G, h1nT); issue(G + 1, h1nT + 4096); issue(G + 2, h1nT + 8192);
            }
            float aq = 0.f;
            for (int c = 0; c < 4; c++) {
                int g = G + c, buf = g % 3;
                MBAR_WAIT(mb + buf * 8, (uint32_t)((g / 3) & 1));
                const float* sx = sXT + buf * 4096 + (khalf * 16) * 128 + lane * 4;
                single16T(sx, sWq + jl * 512 + c * 128 + khalf * 64, aq);
                __syncthreads();
                if (tid == 0 && c + 3 < 4) issue(G + c + 3, h1nT + (c + 3) * 4096);
            }
            G += 4;
            sredf[khalf * 512 + jl * 128 + lane] = aq;
            __syncthreads();
            if (khalf == 0) {
                aq += sredf[512 + jl * 128 + lane];
                g_q[lane * HIDn + j] = aq;
            }
        }
        gsync(++e);

        // ===== Phase 4: scores (HW tanh) =====
        {
#pragma unroll
            for (int r = 0; r < 2; r++) {
                int pi = bid * 16 + w * 2 + r;
                int b = pi >> 6, s = pi & 63;
                const float* qb = g_q + b * HIDn;
                const float* kp = g_kproj + ((size_t)b * Sn + s) * HIDn;
                float acc = 0.f;
#pragma unroll
                for (int i = 0; i < 16; i++) {
                    int h = lane + i * 32;
                    acc = fmaf(vvec[h], tanh_fast(qb[h] + kp[h]), acc);
                }
#pragma unroll
                for (int o = 16; o; o >>= 1) acc += __shfl_xor_sync(0xFFFFFFFFu, acc, o);
                if (lane == 0) g_e[b * Sn + s] = mask[b * Sn + s] ? -1e9f : acc;
            }
        }
        gsync(++e);

        // ===== Phase 5: softmax + ctx =====
        {
            const int b  = bid >> 2;
            const int hs = (bid & 3) * 128;
            if (w == 0) {
                float e0 = g_e[b * Sn + lane];
                float e1 = g_e[b * Sn + 32 + lane];
                float m = fmaxf(e0, e1);
#pragma unroll
                for (int o = 16; o; o >>= 1) m = fmaxf(m, __shfl_xor_sync(0xFFFFFFFFu, m, o));
                float x0 = expf(e0 - m), x1 = expf(e1 - m);
                float ssum = x0 + x1;
#pragma unroll
                for (int o = 16; o; o >>= 1) ssum += __shfl_xor_sync(0xFFFFFFFFu, ssum, o);
                float rinv = 1.f / ssum;
                sA[lane]      = x0 * rinv;
                sA[lane + 32] = x1 * rinv;
            }
            __syncthreads();
            if (tid < 128) {
                int h = hs + tid;
                const float* eb = enc + (size_t)b * Sn * HIDn + h;
                float c = 0.f;
#pragma unroll
                for (int s = 0; s < Sn; s++) c = fmaf(sA[s], eb[(size_t)s * HIDn], c);
                ctxnT[(h >> 2) * 128 + b * 4 + (h & 3)] = c;
                g_dc[((size_t)b * Tn + t) * (2 * HIDn) + HIDn + h] = c;
            }
        }
        gsync(++e);
    }
}

// ---------------- small fp32 GEMM for kproj ----------------
#define GBM 64
#define GBN 64
#define GBK 16
__global__ __launch_bounds__(256) void gemm_abt_kernel(
    const float* __restrict__ A, const float* __restrict__ B,
    float* __restrict__ C, int M, int N, int K)
{
    __shared__ __align__(16) float As[GBK][GBM + 4];
    __shared__ __align__(16) float Bs[GBK][GBN + 4];
    const int tid = threadIdx.x;
    const int rowBase = blockIdx.y * GBM;
    const int colBase = blockIdx.x * GBN;
    const int tm = tid >> 4;
    const int tn = tid & 15;
    const int lr  = tid >> 2;
    const int lk4 = (tid & 3) * 4;

    float acc[4][4];
#pragma unroll
    for (int i = 0; i < 4; i++)
#pragma unroll
        for (int jj = 0; jj < 4; jj++) acc[i][jj] = 0.f;

    const float* Aptr = A + (size_t)(rowBase + lr) * K + lk4;
    const float* Bptr = B + (size_t)(colBase + lr) * K + lk4;
    for (int kt = 0; kt < K; kt += GBK) {
        float4 a4 = *(const float4*)(Aptr + kt);
        float4 b4 = *(const float4*)(Bptr + kt);
        As[lk4 + 0][lr] = a4.x; As[lk4 + 1][lr] = a4.y;
        As[lk4 + 2][lr] = a4.z; As[lk4 + 3][lr] = a4.w;
        Bs[lk4 + 0][lr] = b4.x; Bs[lk4 + 1][lr] = b4.y;
        Bs[lk4 + 2][lr] = b4.z; Bs[lk4 + 3][lr] = b4.w;
        __syncthreads();
#pragma unroll
        for (int kk = 0; kk < GBK; kk++) {
            float4 av = *(const float4*)(&As[kk][tm * 4]);
            float4 bv = *(const float4*)(&Bs[kk][tn * 4]);
            float ar[4] = {av.x, av.y, av.z, av.w};
            float br[4] = {bv.x, bv.y, bv.z, bv.w};
#pragma unroll
            for (int i = 0; i < 4; i++)
#pragma unroll
                for (int jj = 0; jj < 4; jj++)
                    acc[i][jj] = fmaf(ar[i], br[jj], acc[i][jj]);
        }
        __syncthreads();
    }
#pragma unroll
    for (int i = 0; i < 4; i++) {
        float4 o;
        o.x = acc[i][0]; o.y = acc[i][1]; o.z = acc[i][2]; o.w = acc[i][3];
        *(float4*)(C + (size_t)(rowBase + tm * 4 + i) * N + colBase + tn * 4) = o;
    }
}

// ---------------- launch ----------------
extern "C" void kernel_launch(void* const* d_in, const int* in_sizes, int n_in,
                              void* d_out, int out_size)
{
    const float*         enc       = (const float*)d_in[0];
    const unsigned char* src_mask  = (const unsigned char*)d_in[1];
    const int*           tgt_in    = (const int*)d_in[2];
    const float*         emb_table = (const float*)d_in[3];
    const float*         W_ih0     = (const float*)d_in[4];
    const float*         W_hh0     = (const float*)d_in[5];
    const float*         b_ih0     = (const float*)d_in[6];
    const float*         b_hh0     = (const float*)d_in[7];
    const float*         W_ih1     = (const float*)d_in[8];
    const float*         W_hh1     = (const float*)d_in[9];
    const float*         b_ih1     = (const float*)d_in[10];
    const float*         b_hh1     = (const float*)d_in[11];
    const float*         Wq        = (const float*)d_in[12];
    const float*         Wk        = (const float*)d_in[13];
    const float*         vvec      = (const float*)d_in[14];
    const float*         W_out     = (const float*)d_in[15];
    const float*         b_out     = (const float*)d_in[16];
    float*               out       = (float*)d_out;

    float* kproj_ptr = nullptr;
    float* dc_ptr    = nullptr;
    __half *ah_p = nullptr;
    cudaGetSymbolAddress((void**)&kproj_ptr, g_kproj);
    cudaGetSymbolAddress((void**)&dc_ptr, g_dc);
    cudaGetSymbolAddress((void**)&ah_p, g_ah);

    const int smem_bytes = 2 * STGB;   // 65536
    cudaFuncSetAttribute(hmma_gemm_vocab,
                         cudaFuncAttributeMaxDynamicSharedMemorySize, smem_bytes);
    cudaFuncSetAttribute(decoder_persistent,
                         cudaFuncAttributeMaxDynamicSharedMemorySize, DEC_SMEM_B);

    // k_proj = enc_out @ Wk^T
    {
        dim3 grid(HIDn / GBN, (Bn * Sn) / GBM);
        gemm_abt_kernel<<<grid, 256>>>(enc, Wk, kproj_ptr, Bn * Sn, HIDn, HIDn);
    }

    // full recurrence (smem weights + TMA-bulk activation staging) + W-split
    decoder_persistent<<<NBLK + EXTRA, NTHR, DEC_SMEM_B>>>(
        enc, src_mask, tgt_in, emb_table,
        W_ih0, W_hh0, b_ih0, b_hh0,
        W_ih1, W_hh1, b_ih1, b_hh1,
        Wq, vvec, W_out);

    // split dc -> tiled/swizzled fp16 (hi only)
    {
        int nchunks = Bn * Tn * (KV / 8);
        split_h_kernel<<<(nchunks + 255) / 256, 256>>>(dc_ptr, ah_p, nchunks);
    }

    // logits via fp16 1-term HMMA GEMM
    {
        dim3 grid((Bn * Tn) / 128, VOCn / 128);
        hmma_gemm_vocab<<<grid, 256, smem_bytes>>>(b_out, out);
    }
}

// round 16
// speedup vs baseline: 1.0510x; 1.0002x over previous
#include <cuda_runtime.h>
#include <cuda_fp16.h>
#include <math.h>
#include <stdint.h>

#define Bn   32
#define Sn   64
#define Tn   64
#define EMBn 256
#define HIDn 512
#define VOCn 32000
#define KV   1024      // 2*HID

#define NBLK  128      // barrier participants
#define EXTRA 20       // spare blocks doing W-split
#define NTHR  256

// vocab GEMM tiling
#define BKv   64
#define NKC   (KV / BKv)              // 16 k-chunks
#define BLKB  (128 * BKv * 2)         // 16384 bytes per 128x64 fp16 tile block
#define STGB  (2 * BLKB)              // 32768 bytes per stage (Ah, Wh)

// dynamic smem for decoder (floats): 3 x 4096 chunk ring + weights + red + sA
#define DEC_SMEM_F (12288 + 9216 + 6144 + 6144 + 6144 + 2048 + 1024 + 64)
#define DEC_SMEM_B (DEC_SMEM_F * 4)   // 172288 bytes

// ---------------- scratch state (device globals; no allocation) ----------------
__device__ __align__(16) float g_kproj[Bn * Sn * HIDn];
// transposed state: element (k, b) at (k>>2)*128 + b*4 + (k&3)
__device__ __align__(1024) float g_h0T[2][HIDn * Bn];
__device__ __align__(1024) float g_h1T[2][HIDn * Bn];
__device__ __align__(1024) float g_ctxT[2][HIDn * Bn];
__device__ __align__(1024) float g_embT[Tn * EMBn * Bn];   // [t][kg][b][4], 2 MB
__device__ __align__(16) float g_q[Bn * HIDn];
__device__ __align__(16) float g_e[Bn * Sn];
__device__ __align__(16) float g_dc[Bn * Tn * 2 * HIDn];

// tiled+swizzled fp16 panels for the vocab GEMM
__device__ __align__(1024) __half g_wh[(size_t)VOCn * KV];
__device__ __align__(1024) __half g_ah[Bn * Tn * KV];

// contention-free barrier state
__device__ volatile unsigned g_flags[NBLK];
__device__ volatile unsigned g_rel;

// ================= helpers =================
__device__ __forceinline__ uint32_t smem_u32(const void* p) {
    uint32_t a;
    asm("{ .reg .u64 t; cvta.to.shared.u64 t, %1; cvt.u32.u64 %0, t; }" : "=r"(a) : "l"(p));
    return a;
}

#define MBAR_INIT(addr, cnt) \
    asm volatile("mbarrier.init.shared.b64 [%0], %1;" :: "r"(addr), "r"(cnt) : "memory")
#define MBAR_EXPECT_TX(addr, bytes) \
    asm volatile("mbarrier.arrive.expect_tx.shared.b64 _, [%0], %1;" :: "r"(addr), "r"(bytes) : "memory")
#define MBAR_WAIT(addr, parity) do {                                            \
    uint32_t _m = (addr), _p = (parity), _d;                                    \
    asm volatile("{\n\t.reg .pred p;\n\t"                                       \
        "mbarrier.try_wait.parity.acquire.cta.shared::cta.b64 p, [%1], %2;\n\t" \
        "selp.b32 %0, 1, 0, p;\n\t}" : "=r"(_d) : "r"(_m), "r"(_p) : "memory"); \
    if (!_d) {                                                                  \
        asm volatile("{\n\t.reg .pred P1;\n\tWL_%=:\n\t"                        \
            "mbarrier.try_wait.parity.acquire.cta.shared::cta.b64 P1, [%0], %1, 0x989680;\n\t" \
            "@P1 bra.uni WD_%=;\n\tbra.uni WL_%=;\n\tWD_%=:\n\t}"               \
            :: "r"(_m), "r"(_p) : "memory");                                    \
    } } while (0)

__device__ __forceinline__ void bulk_g2s(uint32_t dst, const void* src,
                                         uint32_t bytes, uint32_t bar) {
    asm volatile(
        "cp.async.bulk.shared::cluster.global.mbarrier::complete_tx::bytes "
        "[%0], [%1], %2, [%3];"
        :: "r"(dst), "l"(src), "r"(bytes), "r"(bar) : "memory");
}

__device__ __forceinline__ void ldm4(uint32_t& r0, uint32_t& r1, uint32_t& r2,
                                     uint32_t& r3, uint32_t a) {
    asm volatile("ldmatrix.sync.aligned.m8n8.x4.shared.b16 {%0,%1,%2,%3}, [%4];"
                 : "=r"(r0), "=r"(r1), "=r"(r2), "=r"(r3) : "r"(a));
}

__device__ __forceinline__ void mma_f16(float* c, const uint32_t* a,
                                        uint32_t b0, uint32_t b1) {
    asm volatile(
        "mma.sync.aligned.m16n8k16.row.col.f32.f16.f16.f32 "
        "{%0,%1,%2,%3}, {%4,%5,%6,%7}, {%8,%9}, {%0,%1,%2,%3};"
        : "+f"(c[0]), "+f"(c[1]), "+f"(c[2]), "+f"(c[3])
        : "r"(a[0]), "r"(a[1]), "r"(a[2]), "r"(a[3]), "r"(b0), "r"(b1));
}

__device__ __forceinline__ float tanh_fast(float x) {
    float y;
    asm("tanh.approx.f32 %0, %1;" : "=f"(y) : "f"(x));
    return y;
}

// swizzle within a 16KB GEMM tile block
__device__ __forceinline__ uint32_t swz(uint32_t off) {
    return off ^ (((off >> 7) & 7u) << 4);
}

// ================= split fp32 -> fp16 hi, tiled + swizzled (A panels) =========
__global__ __launch_bounds__(256) void split_h_kernel(
    const float* __restrict__ src, __half* __restrict__ hi, int nchunks)
{
    int id = blockIdx.x * 256 + threadIdx.x;
    if (id >= nchunks) return;
    int n  = id >> 7;
    int k0 = (id & 127) * 8;
    const float* s = src + (size_t)n * KV + k0;
    float4 x0 = *(const float4*)s;
    float4 x1 = *(const float4*)(s + 4);
    float xs[8] = {x0.x, x0.y, x0.z, x0.w, x1.x, x1.y, x1.z, x1.w};

    uint32_t hw[4];
#pragma unroll
    for (int i = 0; i < 4; i++) {
        __half2 hp = __halves2half2(__float2half_rn(xs[2 * i]),
                                    __float2half_rn(xs[2 * i + 1]));
        hw[i] = *(uint32_t*)&hp;
    }

    int nt = n >> 7, r = n & 127, kc = k0 >> 6;
    uint32_t off = swz((uint32_t)(r * 128 + (k0 & 63) * 2));
    size_t blk = ((size_t)nt * NKC + kc) * BLKB;
    *(uint4*)((char*)hi + blk + off) = make_uint4(hw[0], hw[1], hw[2], hw[3]);
}

// ================= HMMA fp16 1-term vocab GEMM (TMA-bulk, 2-stage) ============
__global__ __launch_bounds__(256) void hmma_gemm_vocab(
    const float* __restrict__ bias, float* __restrict__ C)
{
    extern __shared__ __align__(128) char sm[];
    __shared__ __align__(8) uint64_t mbar[2];
    __shared__ float sBias[128];

    const int tid  = threadIdx.x;
    const int wid  = tid >> 5;
    const int lane = tid & 31;
    const int m_t = blockIdx.x, n_t = blockIdx.y;
    const int m0 = m_t * 128,   n0 = n_t * 128;
    const int warp_m = wid & 1;
    const int warp_n = wid >> 1;

    if (tid < 128) sBias[tid] = bias[n0 + tid];

    const uint32_t smb = smem_u32(sm);
    const uint32_t mb  = smem_u32(mbar);

    const char* gA = (const char*)g_ah + (size_t)m_t * NKC * BLKB;
    const char* gH = (const char*)g_wh + (size_t)n_t * NKC * BLKB;

    if (tid == 0) { MBAR_INIT(mb, 1); MBAR_INIT(mb + 8, 1); }
    __syncthreads();

    auto issue = [&](int s, int buf) {
        uint32_t d   = smb + buf * STGB;
        uint32_t bar = mb + buf * 8;
        MBAR_EXPECT_TX(bar, (uint32_t)STGB);
        bulk_g2s(d,        gA + (size_t)s * BLKB, BLKB, bar);
        bulk_g2s(d + BLKB, gH + (size_t)s * BLKB, BLKB, bar);
    };
    if (tid == 0) issue(0, 0);

    float acc[4][4][4];
#pragma unroll
    for (int mt = 0; mt < 4; mt++)
#pragma unroll
        for (int nt = 0; nt < 4; nt++)
#pragma unroll
            for (int r = 0; r < 4; r++) acc[mt][nt][r] = 0.f;

    const int a_row = warp_m * 64 + (lane & 15);
    const int a_cb  = (lane >> 4) * 16;
    const int b_row = warp_n * 32 + ((lane >> 4) << 3) + (lane & 7);
    const int b_cb  = ((lane >> 3) & 1) * 16;

    for (int s = 0; s < NKC; s++) {
        const int buf = s & 1;
        MBAR_WAIT(mb + buf * 8, (uint32_t)((s >> 1) & 1));
        if (tid == 0 && s + 1 < NKC) issue(s + 1, buf ^ 1);

        const uint32_t sA  = smb + buf * STGB;
        const uint32_t sWh = sA + BLKB;

#pragma unroll
        for (int koff = 0; koff < BKv; koff += 16) {
            uint32_t ah[4][4], bh[2][4];
#pragma unroll
            for (int mt = 0; mt < 4; mt++) {
                uint32_t off = swz((uint32_t)((a_row + mt * 16) * 128 +
                                              a_cb + koff * 2));
                ldm4(ah[mt][0], ah[mt][1], ah[mt][2], ah[mt][3], sA + off);
            }
#pragma unroll
            for (int p = 0; p < 2; p++) {
                uint32_t off = swz((uint32_t)((b_row + p * 16) * 128 +
                                              b_cb + koff * 2));
                ldm4(bh[p][0], bh[p][1], bh[p][2], bh[p][3], sWh + off);
            }
#pragma unroll
            for (int mt = 0; mt < 4; mt++) {
#pragma unroll
                for (int nt = 0; nt < 4; nt++) {
                    int p = nt >> 1, h = (nt & 1) * 2;
                    mma_f16(acc[mt][nt], ah[mt], bh[p][h], bh[p][h + 1]);
                }
            }
        }
        __syncthreads();
    }

    const int er = (lane >> 2);
    const int ec = (lane & 3) * 2;
#pragma unroll
    for (int mt = 0; mt < 4; mt++) {
#pragma unroll
        for (int nt = 0; nt < 4; nt++) {
            int row  = m0 + warp_m * 64 + mt * 16 + er;
            int colL = warp_n * 32 + nt * 8 + ec;
            int col  = n0 + colL;
            float2 o0, o1;
            o0.x = acc[mt][nt][0] + sBias[colL];
            o0.y = acc[mt][nt][1] + sBias[colL + 1];
            o1.x = acc[mt][nt][2] + sBias[colL];
            o1.y = acc[mt][nt][3] + sBias[colL + 1];
            *(float2*)(C + (size_t)row * VOCn + col)       = o0;
            *(float2*)(C + (size_t)(row + 8) * VOCn + col) = o1;
        }
    }
}

// ---------------- contention-free grid barrier ----------------
__device__ __forceinline__ void gsync(unsigned e) {
    __syncthreads();
    const int tid = threadIdx.x;
    const int bid = blockIdx.x;
    if (tid == 0) {
        asm volatile("fence.proxy.async;" ::: "memory");
        __threadfence();
        g_flags[bid] = e;
    }
    if (bid == 0) {
        if (tid < NBLK) { while (g_flags[tid] != e) { } }
        __syncthreads();
        if (tid == 0) { __threadfence(); g_rel = e; }
    } else {
        if (tid == 0) { while (g_rel != e) { } __threadfence(); }
    }
    __syncthreads();
}

// ---------------- dot helpers (transposed-chunk x: stride 128 floats) ---------
__device__ __forceinline__ void triple16T(const float* __restrict__ sx,
    const float* __restrict__ w0, const float* __restrict__ w1,
    const float* __restrict__ w2, float& a0, float& a1, float& a2)
{
#pragma unroll
    for (int i = 0; i < 16; i++) {
        float4 x = *(const float4*)(sx + i * 128);
        float4 u = *(const float4*)(w0 + i * 4);
        float4 v = *(const float4*)(w1 + i * 4);
        float4 s = *(const float4*)(w2 + i * 4);
        a0 = fmaf(x.x, u.x, fmaf(x.y, u.y, fmaf(x.z, u.z, fmaf(x.w, u.w, a0))));
        a1 = fmaf(x.x, v.x, fmaf(x.y, v.y, fmaf(x.z, v.z, fmaf(x.w, v.w, a1))));
        a2 = fmaf(x.x, s.x, fmaf(x.y, s.y, fmaf(x.z, s.z, fmaf(x.w, s.w, a2))));
    }
}
__device__ __forceinline__ void single16T(const float* __restrict__ sx,
    const float* __restrict__ w0, float& a0)
{
#pragma unroll
    for (int i = 0; i < 16; i++) {
        float4 x = *(const float4*)(sx + i * 128);
        float4 u = *(const float4*)(w0 + i * 4);
        a0 = fmaf(x.x, u.x, fmaf(x.y, u.y, fmaf(x.z, u.z, fmaf(x.w, u.w, a0))));
    }
}

// ---------------- persistent recurrence kernel (+W-split on spare blocks) -----
// 256 threads: 8 warps = 4 j (jl) x 2 k-halves (khalf). lane = batch.
// Weights in SMEM; activation chunks TMA-bulk staged via 3-buffer ring.
__global__ __launch_bounds__(NTHR, 1) void decoder_persistent(
    const float* __restrict__ enc, const unsigned char* __restrict__ mask,
    const int* __restrict__ tgt, const float* __restrict__ emb,
    const float* __restrict__ Wih0, const float* __restrict__ Whh0,
    const float* __restrict__ bih0, const float* __restrict__ bhh0,
    const float* __restrict__ Wih1, const float* __restrict__ Whh1,
    const float* __restrict__ bih1, const float* __restrict__ bhh1,
    const float* __restrict__ Wq, const float* __restrict__ vvec,
    const float* __restrict__ Wout)
{
    const int tid = threadIdx.x;
    const int bid = blockIdx.x;

    // ===== spare blocks: stream W_out -> fp16 tiled/swizzled panels =====
    if (bid >= NBLK) {
        const int sp  = bid - NBLK;
        const int nch = VOCn * (KV / 8);
        for (int id = sp * NTHR + tid; id < nch; id += EXTRA * NTHR) {
            int n  = id >> 7;
            int k0 = (id & 127) * 8;
            const float* s = Wout + (size_t)n * KV + k0;
            float4 x0 = __ldcs((const float4*)s);
            float4 x1 = __ldcs((const float4*)(s + 4));
            float xs[8] = {x0.x, x0.y, x0.z, x0.w, x1.x, x1.y, x1.z, x1.w};
            uint32_t hw[4];
#pragma unroll
            for (int i = 0; i < 4; i++) {
                __half2 hp = __halves2half2(__float2half_rn(xs[2 * i]),
                                            __float2half_rn(xs[2 * i + 1]));
                hw[i] = *(uint32_t*)&hp;
            }
            int nt = n >> 7, r = n & 127, kc = k0 >> 6;
            uint32_t off = swz((uint32_t)(r * 128 + (k0 & 63) * 2));
            size_t blk = ((size_t)nt * NKC + kc) * BLKB;
            float4 ov = make_float4(__uint_as_float(hw[0]), __uint_as_float(hw[1]),
                                    __uint_as_float(hw[2]), __uint_as_float(hw[3]));
            __stcs((float4*)((char*)g_wh + blk + off), ov);
        }
        return;
    }

    // ===== barrier-participating blocks =====
    extern __shared__ __align__(16) float dsm[];
    float* sXT   = dsm;                       // 3 x 4096 (chunk ring)
    float* sW0   = dsm + 12288;               // [g][jl][768]
    float* sU0   = sW0 + 9216;                // [g][jl][512]
    float* sW1   = sU0 + 6144;
    float* sU1   = sW1 + 6144;
    float* sWq   = sU1 + 6144;                // [jl][512]
    float* sredf = sWq + 2048;                // 1024
    float* sA    = sredf + 1024;              // 64
    __shared__ __align__(8) uint64_t mbar[3];

    const int w     = tid >> 5;
    const int lane  = tid & 31;
    const int jl    = w & 3;
    const int khalf = w >> 2;
    const int j     = bid * 4 + jl;

    const uint32_t sxa = smem_u32(dsm);
    const uint32_t mb  = smem_u32(mbar);

    unsigned e = g_flags[bid];   // replay-safe epoch base

    if (tid == 0) { MBAR_INIT(mb, 1); MBAR_INIT(mb + 8, 1); MBAR_INIT(mb + 16, 1); }

    // ---- one-time weight preload into smem ----
    {
        const int jb = bid * 4;
        for (int i = tid; i < 12 * 192; i += NTHR) {
            int row = i / 192, k4 = (i % 192) * 4;
            int g = row >> 2, jj = row & 3;
            *(float4*)&sW0[g * 3072 + jj * 768 + k4] =
                *(const float4*)(Wih0 + (size_t)(jb + jj + 512 * g) * 768 + k4);
        }
        for (int i = tid; i < 12 * 128; i += NTHR) {
            int row = i / 128, k4 = (i % 128) * 4;
            int g = row >> 2, jj = row & 3;
            *(float4*)&sU0[g * 2048 + jj * 512 + k4] =
                *(const float4*)(Whh0 + (size_t)(jb + jj + 512 * g) * 512 + k4);
            *(float4*)&sW1[g * 2048 + jj * 512 + k4] =
                *(const float4*)(Wih1 + (size_t)(jb + jj + 512 * g) * 512 + k4);
            *(float4*)&sU1[g * 2048 + jj * 512 + k4] =
                *(const float4*)(Whh1 + (size_t)(jb + jj + 512 * g) * 512 + k4);
        }
        for (int i = tid; i < 4 * 128; i += NTHR) {
            int jj = i / 128, k4 = (i % 128) * 4;
            *(float4*)&sWq[jj * 512 + k4] =
                *(const float4*)(Wq + (size_t)(jb + jj) * 512 + k4);
        }
    }

    // ---- one-time transposed embedding gather: g_embT[t][kg][b][4] ----
    for (int i = bid * NTHR + tid; i < Tn * 64 * Bn; i += NBLK * NTHR) {
        int t0 = i >> 11;
        int kg = (i >> 5) & 63;
        int b  = i & 31;
        int tok = tgt[b * Tn + t0];
        float4 v = *(const float4*)(emb + (size_t)tok * EMBn + kg * 4);
        *(float4*)&g_embT[(size_t)t0 * 8192 + kg * 128 + b * 4] = v;
    }

    {
        if (tid < 128) {
            g_h0T[0][bid * 128 + tid]  = 0.f;
            g_h1T[0][bid * 128 + tid]  = 0.f;
            g_ctxT[0][bid * 128 + tid] = 0.f;
        }
    }
    gsync(++e);   // mbar init + weights + embT + zeros all visible

    int G = 0;    // global chunk counter: buf = G%3, parity = (G/3)&1

    auto issue = [&](int gi, const float* src) {
        int buf = gi % 3;
        MBAR_EXPECT_TX(mb + buf * 8, 16384u);
        bulk_g2s(sxa + buf * 16384, src, 16384u, mb + buf * 8);
    };

    for (int t = 0; t < Tn; t++) {
        const int p = t & 1;
        const float* h0pT  = g_h0T[p];     float* h0nT  = g_h0T[1 - p];
        const float* h1pT  = g_h1T[p];     float* h1nT  = g_h1T[1 - p];
        const float* ctxpT = g_ctxT[p];    float* ctxnT = g_ctxT[1 - p];

        // ===== Phase 1: GRU0 (10 chunks) =====
        {
            auto p1src = [&](int c) -> const float* {
                if (c < 2) return g_embT + (size_t)t * 8192 + c * 4096;
                if (c < 6) return ctxpT + (c - 2) * 4096;
                return h0pT + (c - 6) * 4096;
            };
            if (tid == 0) { issue(G, p1src(0)); issue(G + 1, p1src(1)); issue(G + 2, p1src(2)); }
            float ar = 0.f, az = 0.f, anx = 0.f, anh = 0.f;
            for (int c = 0; c < 10; c++) {
                int g = G + c, buf = g % 3;
                MBAR_WAIT(mb + buf * 8, (uint32_t)((g / 3) & 1));
                const float* sx = sXT + buf * 4096 + (khalf * 16) * 128 + lane * 4;
                if (c < 6) {
                    int col = c * 128 + khalf * 64;
                    triple16T(sx, sW0 + 0 * 3072 + jl * 768 + col,
                              sW0 + 1 * 3072 + jl * 768 + col,
                              sW0 + 2 * 3072 + jl * 768 + col, ar, az, anx);
                } else {
                    int col = (c - 6) * 128 + khalf * 64;
                    triple16T(sx, sU0 + 0 * 2048 + jl * 512 + col,
                              sU0 + 1 * 2048 + jl * 512 + col,
                              sU0 + 2 * 2048 + jl * 512 + col, ar, az, anh);
                }
                __syncthreads();
                if (tid == 0 && c + 3 < 10) issue(G + c + 3, p1src(c + 3));
            }
            G += 10;
            sredf[khalf * 512 + jl * 128 + 0 * 32 + lane] = ar;
            sredf[khalf * 512 + jl * 128 + 1 * 32 + lane] = az;
            sredf[khalf * 512 + jl * 128 + 2 * 32 + lane] = anx;
            sredf[khalf * 512 + jl * 128 + 3 * 32 + lane] = anh;
            __syncthreads();
            if (khalf == 0) {
                ar  += sredf[512 + jl * 128 + 0 * 32 + lane];
                az  += sredf[512 + jl * 128 + 1 * 32 + lane];
                anx += sredf[512 + jl * 128 + 2 * 32 + lane];
                anh += sredf[512 + jl * 128 + 3 * 32 + lane];
                float r = 1.f / (1.f + expf(-(ar + bih0[j] + bhh0[j])));
                float z = 1.f / (1.f + expf(-(az + bih0[j + 512] + bhh0[j + 512])));
                float n = tanhf(anx + bih0[j + 1024] + r * (anh + bhh0[j + 1024]));
                float hp = h0pT[bid * 128 + lane * 4 + jl];
                h0nT[bid * 128 + lane * 4 + jl] = (1.f - z) * n + z * hp;
            }
        }
        gsync(++e);

        // ===== Phase 2: GRU1 (8 chunks) =====
        {
            auto p2src = [&](int c) -> const float* {
                return (c < 4) ? (h0nT + c * 4096) : (h1pT + (c - 4) * 4096);
            };
            if (tid == 0) { issue(G, p2src(0)); issue(G + 1, p2src(1)); issue(G + 2, p2src(2)); }
            float ar = 0.f, az = 0.f, anx = 0.f, anh = 0.f;
            for (int c = 0; c < 8; c++) {
                int g = G + c, buf = g % 3;
                MBAR_WAIT(mb + buf * 8, (uint32_t)((g / 3) & 1));
                const float* sx = sXT + buf * 4096 + (khalf * 16) * 128 + lane * 4;
                if (c < 4) {
                    int col = c * 128 + khalf * 64;
                    triple16T(sx, sW1 + 0 * 2048 + jl * 512 + col,
                              sW1 + 1 * 2048 + jl * 512 + col,
                              sW1 + 2 * 2048 + jl * 512 + col, ar, az, anx);
                } else {
                    int col = (c - 4) * 128 + khalf * 64;
                    triple16T(sx, sU1 + 0 * 2048 + jl * 512 + col,
                              sU1 + 1 * 2048 + jl * 512 + col,
                              sU1 + 2 * 2048 + jl * 512 + col, ar, az, anh);
                }
                __syncthreads();
                if (tid == 0 && c + 3 < 8) issue(G + c + 3, p2src(c + 3));
            }
            G += 8;
            sredf[khalf * 512 + jl * 128 + 0 * 32 + lane] = ar;
            sredf[khalf * 512 + jl * 128 + 1 * 32 + lane] = az;
            sredf[khalf * 512 + jl * 128 + 2 * 32 + lane] = anx;
            sredf[khalf * 512 + jl * 128 + 3 * 32 + lane] = anh;
            __syncthreads();
            if (khalf == 0) {
                ar  += sredf[512 + jl * 128 + 0 * 32 + lane];
                az  += sredf[512 + jl * 128 + 1 * 32 + lane];
                anx += sredf[512 + jl * 128 + 2 * 32 + lane];
                anh += sredf[512 + jl * 128 + 3 * 32 + lane];
                float r = 1.f / (1.f + expf(-(ar + bih1[j] + bhh1[j])));
                float z = 1.f / (1.f + expf(-(az + bih1[j + 512] + bhh1[j + 512])));
                float n = tanhf(anx + bih1[j + 1024] + r * (anh + bhh1[j + 1024]));
                float hp = h1pT[bid * 128 + lane * 4 + jl];
                float hnew = (1.f - z) * n + z * hp;
                h1nT[bid * 128 + lane * 4 + jl] = hnew;
                g_dc[((size_t)lane * Tn + t) * (2 * HIDn) + j] = hnew;
            }
        }
        gsync(++e);

        // ===== Phase 3: q = dec @ Wq^T (4 chunks) =====
        {
            if (tid == 0) {
                issue(G, h1nT); issue(G + 1, h1nT + 4096); issue(G + 2, h1nT + 8192);
            }
            float aq = 0.f;
            for (int c = 0; c < 4; c++) {
                int g = G + c, buf = g % 3;
                MBAR_WAIT(mb + buf * 8, (uint32_t)((g / 3) & 1));
                const float* sx = sXT + buf * 4096 + (khalf * 16) * 128 + lane * 4;
                single16T(sx, sWq + jl * 512 + c * 128 + khalf * 64, aq);
                __syncthreads();
                if (tid == 0 && c + 3 < 4) issue(G + c + 3, h1nT + (c + 3) * 4096);
            }
            G += 4;
            sredf[khalf * 512 + jl * 128 + lane] = aq;
            __syncthreads();
            if (khalf == 0) {
                aq += sredf[512 + jl * 128 + lane];
                g_q[lane * HIDn + j] = aq;
            }
        }
        gsync(++e);

        // ===== Phase 4: scores (HW tanh) =====
        {
#pragma unroll
            for (int r = 0; r < 2; r++) {
                int pi = bid * 16 + w * 2 + r;
                int b = pi >> 6, s = pi & 63;
                const float* qb = g_q + b * HIDn;
                const float* kp = g_kproj + ((size_t)b * Sn + s) * HIDn;
                float acc = 0.f;
#pragma unroll
                for (int i = 0; i < 16; i++) {
                    int h = lane + i * 32;
                    acc = fmaf(vvec[h], tanh_fast(qb[h] + kp[h]), acc);
                }
#pragma unroll
                for (int o = 16; o; o >>= 1) acc += __shfl_xor_sync(0xFFFFFFFFu, acc, o);
                if (lane == 0) g_e[b * Sn + s] = mask[b * Sn + s] ? -1e9f : acc;
            }
        }
        gsync(++e);

        // ===== Phase 5: softmax + ctx =====
        {
            const int b  = bid >> 2;
            const int hs = (bid & 3) * 128;
            if (w == 0) {
                float e0 = g_e[b * Sn + lane];
                float e1 = g_e[b * Sn + 32 + lane];
                float m = fmaxf(e0, e1);
#pragma unroll
                for (int o = 16; o; o >>= 1) m = fmaxf(m, __shfl_xor_sync(0xFFFFFFFFu, m, o));
                float x0 = expf(e0 - m), x1 = expf(e1 - m);
                float ssum = x0 + x1;
#pragma unroll
                for (int o = 16; o; o >>= 1) ssum += __shfl_xor_sync(0xFFFFFFFFu, ssum, o);
                float rinv = 1.f / ssum;
                sA[lane]      = x0 * rinv;
                sA[lane + 32] = x1 * rinv;
            }
            __syncthreads();
            if (tid < 128) {
                int h = hs + tid;
                const float* eb = enc + (size_t)b * Sn * HIDn + h;
                float c = 0.f;
#pragma unroll
                for (int s = 0; s < Sn; s++) c = fmaf(sA[s], eb[(size_t)s * HIDn], c);
                ctxnT[(h >> 2) * 128 + b * 4 + (h & 3)] = c;
                g_dc[((size_t)b * Tn + t) * (2 * HIDn) + HIDn + h] = c;
            }
        }
        gsync(++e);
    }
}

// ---------------- small fp32 GEMM for kproj ----------------
#define GBM 64
#define GBN 64
#define GBK 16
__global__ __launch_bounds__(256) void gemm_abt_kernel(
    const float* __restrict__ A, const float* __restrict__ B,
    float* __restrict__ C, int M, int N, int K)
{
    __shared__ __align__(16) float As[GBK][GBM + 4];
    __shared__ __align__(16) float Bs[GBK][GBN + 4];
    const int tid = threadIdx.x;
    const int rowBase = blockIdx.y * GBM;
    const int colBase = blockIdx.x * GBN;
    const int tm = tid >> 4;
    const int tn = tid & 15;
    const int lr  = tid >> 2;
    const int lk4 = (tid & 3) * 4;

    float acc[4][4];
#pragma unroll
    for (int i = 0; i < 4; i++)
#pragma unroll
        for (int jj = 0; jj < 4; jj++) acc[i][jj] = 0.f;

    const float* Aptr = A + (size_t)(rowBase + lr) * K + lk4;
    const float* Bptr = B + (size_t)(colBase + lr) * K + lk4;
    for (int kt = 0; kt < K; kt += GBK) {
        float4 a4 = *(const float4*)(Aptr + kt);
        float4 b4 = *(const float4*)(Bptr + kt);
        As[lk4 + 0][lr] = a4.x; As[lk4 + 1][lr] = a4.y;
        As[lk4 + 2][lr] = a4.z; As[lk4 + 3][lr] = a4.w;
        Bs[lk4 + 0][lr] = b4.x; Bs[lk4 + 1][lr] = b4.y;
        Bs[lk4 + 2][lr] = b4.z; Bs[lk4 + 3][lr] = b4.w;
        __syncthreads();
#pragma unroll
        for (int kk = 0; kk < GBK; kk++) {
            float4 av = *(const float4*)(&As[kk][tm * 4]);
            float4 bv = *(const float4*)(&Bs[kk][tn * 4]);
            float ar[4] = {av.x, av.y, av.z, av.w};
            float br[4] = {bv.x, bv.y, bv.z, bv.w};
#pragma unroll
            for (int i = 0; i < 4; i++)
#pragma unroll
                for (int jj = 0; jj < 4; jj++)
                    acc[i][jj] = fmaf(ar[i], br[jj], acc[i][jj]);
        }
        __syncthreads();
    }
#pragma unroll
    for (int i = 0; i < 4; i++) {
        float4 o;
        o.x = acc[i][0]; o.y = acc[i][1]; o.z = acc[i][2]; o.w = acc[i][3];
        *(float4*)(C + (size_t)(rowBase + tm * 4 + i) * N + colBase + tn * 4) = o;
    }
}

// ---------------- launch ----------------
extern "C" void kernel_launch(void* const* d_in, const int* in_sizes, int n_in,
                              void* d_out, int out_size)
{
    const float*         enc       = (const float*)d_in[0];
    const unsigned char* src_mask  = (const unsigned char*)d_in[1];
    const int*           tgt_in    = (const int*)d_in[2];
    const float*         emb_table = (const float*)d_in[3];
    const float*         W_ih0     = (const float*)d_in[4];
    const float*         W_hh0     = (const float*)d_in[5];
    const float*         b_ih0     = (const float*)d_in[6];
    const float*         b_hh0     = (const float*)d_in[7];
    const float*         W_ih1     = (const float*)d_in[8];
    const float*         W_hh1     = (const float*)d_in[9];
    const float*         b_ih1     = (const float*)d_in[10];
    const float*         b_hh1     = (const float*)d_in[11];
    const float*         Wq        = (const float*)d_in[12];
    const float*         Wk        = (const float*)d_in[13];
    const float*         vvec      = (const float*)d_in[14];
    const float*         W_out     = (const float*)d_in[15];
    const float*         b_out     = (const float*)d_in[16];
    float*               out       = (float*)d_out;

    float* kproj_ptr = nullptr;
    float* dc_ptr    = nullptr;
    __half *ah_p = nullptr;
    cudaGetSymbolAddress((void**)&kproj_ptr, g_kproj);
    cudaGetSymbolAddress((void**)&dc_ptr, g_dc);
    cudaGetSymbolAddress((void**)&ah_p, g_ah);

    const int smem_bytes = 2 * STGB;   // 65536
    cudaFuncSetAttribute(hmma_gemm_vocab,
                         cudaFuncAttributeMaxDynamicSharedMemorySize, smem_bytes);
    cudaFuncSetAttribute(decoder_persistent,
                         cudaFuncAttributeMaxDynamicSharedMemorySize, DEC_SMEM_B);

    // k_proj = enc_out @ Wk^T
    {
        dim3 grid(HIDn / GBN, (Bn * Sn) / GBM);
        gemm_abt_kernel<<<grid, 256>>>(enc, Wk, kproj_ptr, Bn * Sn, HIDn, HIDn);
    }

    // full recurrence (smem weights + TMA-bulk activation staging) + W-split
    decoder_persistent<<<NBLK + EXTRA, NTHR, DEC_SMEM_B>>>(
        enc, src_mask, tgt_in, emb_table,
        W_ih0, W_hh0, b_ih0, b_hh0,
        W_ih1, W_hh1, b_ih1, b_hh1,
        Wq, vvec, W_out);

    // split dc -> tiled/swizzled fp16 (hi only)
    {
        int nchunks = Bn * Tn * (KV / 8);
        split_h_kernel<<<(nchunks + 255) / 256, 256>>>(dc_ptr, ah_p, nchunks);
    }

    // logits via fp16 1-term HMMA GEMM
    {
        dim3 grid((Bn * Tn) / 128, VOCn / 128);
        hmma_gemm_vocab<<<grid, 256, smem_bytes>>>(b_out, out);
    }
}

// round 17
// speedup vs baseline: 1.1058x; 1.0522x over previous
#include <cuda_runtime.h>
#include <cuda_fp16.h>
#include <math.h>
#include <stdint.h>

#define Bn   32
#define Sn   64
#define Tn   64
#define EMBn 256
#define HIDn 512
#define VOCn 32000
#define KV   1024      // 2*HID

#define NBLK  128      // barrier participants
#define EXTRA 20       // spare blocks doing W-split
#define NTHR  256

// vocab GEMM tiling
#define BKv   64
#define NKC   (KV / BKv)              // 16 k-chunks
#define BLKB  (128 * BKv * 2)         // 16384 bytes per 128x64 fp16 tile block
#define STGB  (2 * BLKB)              // 32768 bytes per stage (Ah, Wh)

// dynamic smem for decoder (floats): 3 x 4096 chunk ring + weights + red + sA
#define DEC_SMEM_F (12288 + 9216 + 6144 + 6144 + 6144 + 2048 + 1024 + 64)
#define DEC_SMEM_B (DEC_SMEM_F * 4)   // 172288 bytes

// ---------------- scratch state (device globals; no allocation) ----------------
__device__ __align__(16) float g_kproj[Bn * Sn * HIDn];
// transposed state: element (k, b) at (k>>2)*128 + b*4 + (k&3)
__device__ __align__(1024) float g_h0T[2][HIDn * Bn];
__device__ __align__(1024) float g_h1T[2][HIDn * Bn];
__device__ __align__(1024) float g_ctxT[2][HIDn * Bn];
__device__ __align__(1024) float g_embT[Tn * EMBn * Bn];   // [t][kg][b][4], 2 MB
__device__ __align__(16) float g_q[Bn * HIDn];
__device__ __align__(16) float g_e[Bn * Sn];
__device__ __align__(16) float g_dc[Bn * Tn * 2 * HIDn];

// tiled+swizzled fp16 panels for the vocab GEMM
__device__ __align__(1024) __half g_wh[(size_t)VOCn * KV];
__device__ __align__(1024) __half g_ah[Bn * Tn * KV];

// contention-free barrier state
__device__ volatile unsigned g_flags[NBLK];
__device__ volatile unsigned g_rel;

// ================= helpers =================
__device__ __forceinline__ uint32_t smem_u32(const void* p) {
    uint32_t a;
    asm("{ .reg .u64 t; cvta.to.shared.u64 t, %1; cvt.u32.u64 %0, t; }" : "=r"(a) : "l"(p));
    return a;
}

#define MBAR_INIT(addr, cnt) \
    asm volatile("mbarrier.init.shared.b64 [%0], %1;" :: "r"(addr), "r"(cnt) : "memory")
#define MBAR_EXPECT_TX(addr, bytes) \
    asm volatile("mbarrier.arrive.expect_tx.shared.b64 _, [%0], %1;" :: "r"(addr), "r"(bytes) : "memory")
#define MBAR_WAIT(addr, parity) do {                                            \
    uint32_t _m = (addr), _p = (parity), _d;                                    \
    asm volatile("{\n\t.reg .pred p;\n\t"                                       \
        "mbarrier.try_wait.parity.acquire.cta.shared::cta.b64 p, [%1], %2;\n\t" \
        "selp.b32 %0, 1, 0, p;\n\t}" : "=r"(_d) : "r"(_m), "r"(_p) : "memory"); \
    if (!_d) {                                                                  \
        asm volatile("{\n\t.reg .pred P1;\n\tWL_%=:\n\t"                        \
            "mbarrier.try_wait.parity.acquire.cta.shared::cta.b64 P1, [%0], %1, 0x989680;\n\t" \
            "@P1 bra.uni WD_%=;\n\tbra.uni WL_%=;\n\tWD_%=:\n\t}"               \
            :: "r"(_m), "r"(_p) : "memory");                                    \
    } } while (0)

__device__ __forceinline__ void bulk_g2s(uint32_t dst, const void* src,
                                         uint32_t bytes, uint32_t bar) {
    asm volatile(
        "cp.async.bulk.shared::cluster.global.mbarrier::complete_tx::bytes "
        "[%0], [%1], %2, [%3];"
        :: "r"(dst), "l"(src), "r"(bytes), "r"(bar) : "memory");
}

__device__ __forceinline__ void ldm4(uint32_t& r0, uint32_t& r1, uint32_t& r2,
                                     uint32_t& r3, uint32_t a) {
    asm volatile("ldmatrix.sync.aligned.m8n8.x4.shared.b16 {%0,%1,%2,%3}, [%4];"
                 : "=r"(r0), "=r"(r1), "=r"(r2), "=r"(r3) : "r"(a));
}

__device__ __forceinline__ void mma_f16(float* c, const uint32_t* a,
                                        uint32_t b0, uint32_t b1) {
    asm volatile(
        "mma.sync.aligned.m16n8k16.row.col.f32.f16.f16.f32 "
        "{%0,%1,%2,%3}, {%4,%5,%6,%7}, {%8,%9}, {%0,%1,%2,%3};"
        : "+f"(c[0]), "+f"(c[1]), "+f"(c[2]), "+f"(c[3])
        : "r"(a[0]), "r"(a[1]), "r"(a[2]), "r"(a[3]), "r"(b0), "r"(b1));
}

__device__ __forceinline__ float tanh_fast(float x) {
    float y;
    asm("tanh.approx.f32 %0, %1;" : "=f"(y) : "f"(x));
    return y;
}

// swizzle within a 16KB GEMM tile block
__device__ __forceinline__ uint32_t swz(uint32_t off) {
    return off ^ (((off >> 7) & 7u) << 4);
}

// ================= split fp32 -> fp16 hi, tiled + swizzled (A panels) =========
__global__ __launch_bounds__(256) void split_h_kernel(
    const float* __restrict__ src, __half* __restrict__ hi, int nchunks)
{
    int id = blockIdx.x * 256 + threadIdx.x;
    if (id >= nchunks) return;
    int n  = id >> 7;
    int k0 = (id & 127) * 8;
    const float* s = src + (size_t)n * KV + k0;
    float4 x0 = *(const float4*)s;
    float4 x1 = *(const float4*)(s + 4);
    float xs[8] = {x0.x, x0.y, x0.z, x0.w, x1.x, x1.y, x1.z, x1.w};

    uint32_t hw[4];
#pragma unroll
    for (int i = 0; i < 4; i++) {
        __half2 hp = __halves2half2(__float2half_rn(xs[2 * i]),
                                    __float2half_rn(xs[2 * i + 1]));
        hw[i] = *(uint32_t*)&hp;
    }

    int nt = n >> 7, r = n & 127, kc = k0 >> 6;
    uint32_t off = swz((uint32_t)(r * 128 + (k0 & 63) * 2));
    size_t blk = ((size_t)nt * NKC + kc) * BLKB;
    *(uint4*)((char*)hi + blk + off) = make_uint4(hw[0], hw[1], hw[2], hw[3]);
}

// ================= HMMA fp16 1-term vocab GEMM (TMA-bulk, 2-stage) ============
__global__ __launch_bounds__(256) void hmma_gemm_vocab(
    const float* __restrict__ bias, float* __restrict__ C)
{
    extern __shared__ __align__(128) char sm[];
    __shared__ __align__(8) uint64_t mbar[2];
    __shared__ float sBias[128];

    const int tid  = threadIdx.x;
    const int wid  = tid >> 5;
    const int lane = tid & 31;
    const int m_t = blockIdx.x, n_t = blockIdx.y;
    const int m0 = m_t * 128,   n0 = n_t * 128;
    const int warp_m = wid & 1;
    const int warp_n = wid >> 1;

    if (tid < 128) sBias[tid] = bias[n0 + tid];

    const uint32_t smb = smem_u32(sm);
    const uint32_t mb  = smem_u32(mbar);

    const char* gA = (const char*)g_ah + (size_t)m_t * NKC * BLKB;
    const char* gH = (const char*)g_wh + (size_t)n_t * NKC * BLKB;

    if (tid == 0) { MBAR_INIT(mb, 1); MBAR_INIT(mb + 8, 1); }
    __syncthreads();

    auto issue = [&](int s, int buf) {
        uint32_t d   = smb + buf * STGB;
        uint32_t bar = mb + buf * 8;
        MBAR_EXPECT_TX(bar, (uint32_t)STGB);
        bulk_g2s(d,        gA + (size_t)s * BLKB, BLKB, bar);
        bulk_g2s(d + BLKB, gH + (size_t)s * BLKB, BLKB, bar);
    };
    if (tid == 0) issue(0, 0);

    float acc[4][4][4];
#pragma unroll
    for (int mt = 0; mt < 4; mt++)
#pragma unroll
        for (int nt = 0; nt < 4; nt++)
#pragma unroll
            for (int r = 0; r < 4; r++) acc[mt][nt][r] = 0.f;

    const int a_row = warp_m * 64 + (lane & 15);
    const int a_cb  = (lane >> 4) * 16;
    const int b_row = warp_n * 32 + ((lane >> 4) << 3) + (lane & 7);
    const int b_cb  = ((lane >> 3) & 1) * 16;

    for (int s = 0; s < NKC; s++) {
        const int buf = s & 1;
        MBAR_WAIT(mb + buf * 8, (uint32_t)((s >> 1) & 1));
        if (tid == 0 && s + 1 < NKC) issue(s + 1, buf ^ 1);

        const uint32_t sA  = smb + buf * STGB;
        const uint32_t sWh = sA + BLKB;

#pragma unroll
        for (int koff = 0; koff < BKv; koff += 16) {
            uint32_t ah[4][4], bh[2][4];
#pragma unroll
            for (int mt = 0; mt < 4; mt++) {
                uint32_t off = swz((uint32_t)((a_row + mt * 16) * 128 +
                                              a_cb + koff * 2));
                ldm4(ah[mt][0], ah[mt][1], ah[mt][2], ah[mt][3], sA + off);
            }
#pragma unroll
            for (int p = 0; p < 2; p++) {
                uint32_t off = swz((uint32_t)((b_row + p * 16) * 128 +
                                              b_cb + koff * 2));
                ldm4(bh[p][0], bh[p][1], bh[p][2], bh[p][3], sWh + off);
            }
#pragma unroll
            for (int mt = 0; mt < 4; mt++) {
#pragma unroll
                for (int nt = 0; nt < 4; nt++) {
                    int p = nt >> 1, h = (nt & 1) * 2;
                    mma_f16(acc[mt][nt], ah[mt], bh[p][h], bh[p][h + 1]);
                }
            }
        }
        __syncthreads();
    }

    const int er = (lane >> 2);
    const int ec = (lane & 3) * 2;
#pragma unroll
    for (int mt = 0; mt < 4; mt++) {
#pragma unroll
        for (int nt = 0; nt < 4; nt++) {
            int row  = m0 + warp_m * 64 + mt * 16 + er;
            int colL = warp_n * 32 + nt * 8 + ec;
            int col  = n0 + colL;
            float2 o0, o1;
            o0.x = acc[mt][nt][0] + sBias[colL];
            o0.y = acc[mt][nt][1] + sBias[colL + 1];
            o1.x = acc[mt][nt][2] + sBias[colL];
            o1.y = acc[mt][nt][3] + sBias[colL + 1];
            *(float2*)(C + (size_t)row * VOCn + col)       = o0;
            *(float2*)(C + (size_t)(row + 8) * VOCn + col) = o1;
        }
    }
}

// ---------------- contention-free grid barrier ----------------
__device__ __forceinline__ void gsync(unsigned e) {
    __syncthreads();
    const int tid = threadIdx.x;
    const int bid = blockIdx.x;
    if (tid == 0) {
        asm volatile("fence.proxy.async;" ::: "memory");
        __threadfence();
        g_flags[bid] = e;
    }
    if (bid == 0) {
        if (tid < NBLK) { while (g_flags[tid] != e) { } }
        __syncthreads();
        if (tid == 0) { __threadfence(); g_rel = e; }
    } else {
        if (tid == 0) { while (g_rel != e) { } __threadfence(); }
    }
    __syncthreads();
}

// ---------------- dot helpers (transposed-chunk x: stride 128 floats) ---------
__device__ __forceinline__ void triple16T(const float* __restrict__ sx,
    const float* __restrict__ w0, const float* __restrict__ w1,
    const float* __restrict__ w2, float& a0, float& a1, float& a2)
{
#pragma unroll
    for (int i = 0; i < 16; i++) {
        float4 x = *(const float4*)(sx + i * 128);
        float4 u = *(const float4*)(w0 + i * 4);
        float4 v = *(const float4*)(w1 + i * 4);
        float4 s = *(const float4*)(w2 + i * 4);
        a0 = fmaf(x.x, u.x, fmaf(x.y, u.y, fmaf(x.z, u.z, fmaf(x.w, u.w, a0))));
        a1 = fmaf(x.x, v.x, fmaf(x.y, v.y, fmaf(x.z, v.z, fmaf(x.w, v.w, a1))));
        a2 = fmaf(x.x, s.x, fmaf(x.y, s.y, fmaf(x.z, s.z, fmaf(x.w, s.w, a2))));
    }
}
__device__ __forceinline__ void single16T(const float* __restrict__ sx,
    const float* __restrict__ w0, float& a0)
{
#pragma unroll
    for (int i = 0; i < 16; i++) {
        float4 x = *(const float4*)(sx + i * 128);
        float4 u = *(const float4*)(w0 + i * 4);
        a0 = fmaf(x.x, u.x, fmaf(x.y, u.y, fmaf(x.z, u.z, fmaf(x.w, u.w, a0))));
    }
}

// ---------------- persistent recurrence kernel (+W-split on spare blocks) -----
// 256 threads: 8 warps = 4 j (jl) x 2 k-halves (khalf). lane = batch.
// Weights in SMEM; activation chunks TMA-bulk staged via 3-buffer ring.
__global__ __launch_bounds__(NTHR, 1) void decoder_persistent(
    const float* __restrict__ enc, const unsigned char* __restrict__ mask,
    const int* __restrict__ tgt, const float* __restrict__ emb,
    const float* __restrict__ Wih0, const float* __restrict__ Whh0,
    const float* __restrict__ bih0, const float* __restrict__ bhh0,
    const float* __restrict__ Wih1, const float* __restrict__ Whh1,
    const float* __restrict__ bih1, const float* __restrict__ bhh1,
    const float* __restrict__ Wq, const float* __restrict__ vvec,
    const float* __restrict__ Wout)
{
    const int tid = threadIdx.x;
    const int bid = blockIdx.x;

    // ===== spare blocks: stream W_out -> fp16 tiled/swizzled panels =====
    if (bid >= NBLK) {
        const int sp  = bid - NBLK;
        const int nch = VOCn * (KV / 8);
        for (int id = sp * NTHR + tid; id < nch; id += EXTRA * NTHR) {
            int n  = id >> 7;
            int k0 = (id & 127) * 8;
            const float* s = Wout + (size_t)n * KV + k0;
            float4 x0 = __ldcs((const float4*)s);
            float4 x1 = __ldcs((const float4*)(s + 4));
            float xs[8] = {x0.x, x0.y, x0.z, x0.w, x1.x, x1.y, x1.z, x1.w};
            uint32_t hw[4];
#pragma unroll
            for (int i = 0; i < 4; i++) {
                __half2 hp = __halves2half2(__float2half_rn(xs[2 * i]),
                                            __float2half_rn(xs[2 * i + 1]));
                hw[i] = *(uint32_t*)&hp;
            }
            int nt = n >> 7, r = n & 127, kc = k0 >> 6;
            uint32_t off = swz((uint32_t)(r * 128 + (k0 & 63) * 2));
            size_t blk = ((size_t)nt * NKC + kc) * BLKB;
            float4 ov = make_float4(__uint_as_float(hw[0]), __uint_as_float(hw[1]),
                                    __uint_as_float(hw[2]), __uint_as_float(hw[3]));
            __stcs((float4*)((char*)g_wh + blk + off), ov);
        }
        return;
    }

    // ===== barrier-participating blocks =====
    extern __shared__ __align__(16) float dsm[];
    float* sXT   = dsm;                       // 3 x 4096 (chunk ring)
    float* sW0   = dsm + 12288;               // [g][jl][768]
    float* sU0   = sW0 + 9216;                // [g][jl][512]
    float* sW1   = sU0 + 6144;
    float* sU1   = sW1 + 6144;
    float* sWq   = sU1 + 6144;                // [jl][512]
    float* sredf = sWq + 2048;                // 1024
    float* sA    = sredf + 1024;              // 64
    __shared__ __align__(8) uint64_t mbar[3];

    const int w     = tid >> 5;
    const int lane  = tid & 31;
    const int jl    = w & 3;
    const int khalf = w >> 2;
    const int j     = bid * 4 + jl;

    const uint32_t sxa = smem_u32(dsm);
    const uint32_t mb  = smem_u32(mbar);

    unsigned e = g_flags[bid];   // replay-safe epoch base

    if (tid == 0) { MBAR_INIT(mb, 1); MBAR_INIT(mb + 8, 1); MBAR_INIT(mb + 16, 1); }

    // ---- one-time weight preload into smem ----
    {
        const int jb = bid * 4;
        for (int i = tid; i < 12 * 192; i += NTHR) {
            int row = i / 192, k4 = (i % 192) * 4;
            int g = row >> 2, jj = row & 3;
            *(float4*)&sW0[g * 3072 + jj * 768 + k4] =
                *(const float4*)(Wih0 + (size_t)(jb + jj + 512 * g) * 768 + k4);
        }
        for (int i = tid; i < 12 * 128; i += NTHR) {
            int row = i / 128, k4 = (i % 128) * 4;
            int g = row >> 2, jj = row & 3;
            *(float4*)&sU0[g * 2048 + jj * 512 + k4] =
                *(const float4*)(Whh0 + (size_t)(jb + jj + 512 * g) * 512 + k4);
            *(float4*)&sW1[g * 2048 + jj * 512 + k4] =
                *(const float4*)(Wih1 + (size_t)(jb + jj + 512 * g) * 512 + k4);
            *(float4*)&sU1[g * 2048 + jj * 512 + k4] =
                *(const float4*)(Whh1 + (size_t)(jb + jj + 512 * g) * 512 + k4);
        }
        for (int i = tid; i < 4 * 128; i += NTHR) {
            int jj = i / 128, k4 = (i % 128) * 4;
            *(float4*)&sWq[jj * 512 + k4] =
                *(const float4*)(Wq + (size_t)(jb + jj) * 512 + k4);
        }
    }

    // ---- one-time transposed embedding gather: g_embT[t][kg][b][4] ----
    for (int i = bid * NTHR + tid; i < Tn * 64 * Bn; i += NBLK * NTHR) {
        int t0 = i >> 11;
        int kg = (i >> 5) & 63;
        int b  = i & 31;
        int tok = tgt[b * Tn + t0];
        float4 v = *(const float4*)(emb + (size_t)tok * EMBn + kg * 4);
        *(float4*)&g_embT[(size_t)t0 * 8192 + kg * 128 + b * 4] = v;
    }

    {
        if (tid < 128) {
            g_h0T[0][bid * 128 + tid]  = 0.f;
            g_h1T[0][bid * 128 + tid]  = 0.f;
            g_ctxT[0][bid * 128 + tid] = 0.f;
        }
    }
    gsync(++e);   // mbar init + weights + embT + zeros all visible

    int G = 0;    // global chunk counter: buf = G%3, parity = (G/3)&1

    auto issue = [&](int gi, const float* src) {
        int buf = gi % 3;
        MBAR_EXPECT_TX(mb + buf * 8, 16384u);
        bulk_g2s(sxa + buf * 16384, src, 16384u, mb + buf * 8);
    };

    for (int t = 0; t < Tn; t++) {
        const int p = t & 1;
        const float* h0pT  = g_h0T[p];     float* h0nT  = g_h0T[1 - p];
        const float* h1pT  = g_h1T[p];     float* h1nT  = g_h1T[1 - p];
        const float* ctxpT = g_ctxT[p];    float* ctxnT = g_ctxT[1 - p];

        // ===== Phase 1: GRU0 (10 chunks) =====
        {
            auto p1src = [&](int c) -> const float* {
                if (c < 2) return g_embT + (size_t)t * 8192 + c * 4096;
                if (c < 6) return ctxpT + (c - 2) * 4096;
                return h0pT + (c - 6) * 4096;
            };
            if (tid == 0) { issue(G, p1src(0)); issue(G + 1, p1src(1)); issue(G + 2, p1src(2)); }
            float ar = 0.f, az = 0.f, anx = 0.f, anh = 0.f;
            for (int c = 0; c < 10; c++) {
                int g = G + c, buf = g % 3;
                MBAR_WAIT(mb + buf * 8, (uint32_t)((g / 3) & 1));
                const float* sx = sXT + buf * 4096 + (khalf * 16) * 128 + lane * 4;
                if (c < 6) {
                    int col = c * 128 + khalf * 64;
                    triple16T(sx, sW0 + 0 * 3072 + jl * 768 + col,
                              sW0 + 1 * 3072 + jl * 768 + col,
                              sW0 + 2 * 3072 + jl * 768 + col, ar, az, anx);
                } else {
                    int col = (c - 6) * 128 + khalf * 64;
                    triple16T(sx, sU0 + 0 * 2048 + jl * 512 + col,
                              sU0 + 1 * 2048 + jl * 512 + col,
                              sU0 + 2 * 2048 + jl * 512 + col, ar, az, anh);
                }
                __syncthreads();
                if (tid == 0 && c + 3 < 10) issue(G + c + 3, p1src(c + 3));
            }
            G += 10;
            sredf[khalf * 512 + jl * 128 + 0 * 32 + lane] = ar;
            sredf[khalf * 512 + jl * 128 + 1 * 32 + lane] = az;
            sredf[khalf * 512 + jl * 128 + 2 * 32 + lane] = anx;
            sredf[khalf * 512 + jl * 128 + 3 * 32 + lane] = anh;
            __syncthreads();
            if (khalf == 0) {
                ar  += sredf[512 + jl * 128 + 0 * 32 + lane];
                az  += sredf[512 + jl * 128 + 1 * 32 + lane];
                anx += sredf[512 + jl * 128 + 2 * 32 + lane];
                anh += sredf[512 + jl * 128 + 3 * 32 + lane];
                float r = 1.f / (1.f + expf(-(ar + bih0[j] + bhh0[j])));
                float z = 1.f / (1.f + expf(-(az + bih0[j + 512] + bhh0[j + 512])));
                float n = tanhf(anx + bih0[j + 1024] + r * (anh + bhh0[j + 1024]));
                float hp = h0pT[bid * 128 + lane * 4 + jl];
                h0nT[bid * 128 + lane * 4 + jl] = (1.f - z) * n + z * hp;
            }
        }
        gsync(++e);

        // ===== Phase 2: GRU1 (8 chunks) =====
        {
            auto p2src = [&](int c) -> const float* {
                return (c < 4) ? (h0nT + c * 4096) : (h1pT + (c - 4) * 4096);
            };
            if (tid == 0) { issue(G, p2src(0)); issue(G + 1, p2src(1)); issue(G + 2, p2src(2)); }
            float ar = 0.f, az = 0.f, anx = 0.f, anh = 0.f;
            for (int c = 0; c < 8; c++) {
                int g = G + c, buf = g % 3;
                MBAR_WAIT(mb + buf * 8, (uint32_t)((g / 3) & 1));
                const float* sx = sXT + buf * 4096 + (khalf * 16) * 128 + lane * 4;
                if (c < 4) {
                    int col = c * 128 + khalf * 64;
                    triple16T(sx, sW1 + 0 * 2048 + jl * 512 + col,
                              sW1 + 1 * 2048 + jl * 512 + col,
                              sW1 + 2 * 2048 + jl * 512 + col, ar, az, anx);
                } else {
                    int col = (c - 4) * 128 + khalf * 64;
                    triple16T(sx, sU1 + 0 * 2048 + jl * 512 + col,
                              sU1 + 1 * 2048 + jl * 512 + col,
                              sU1 + 2 * 2048 + jl * 512 + col, ar, az, anh);
                }
                __syncthreads();
                if (tid == 0 && c + 3 < 8) issue(G + c + 3, p2src(c + 3));
            }
            G += 8;
            sredf[khalf * 512 + jl * 128 + 0 * 32 + lane] = ar;
            sredf[khalf * 512 + jl * 128 + 1 * 32 + lane] = az;
            sredf[khalf * 512 + jl * 128 + 2 * 32 + lane] = anx;
            sredf[khalf * 512 + jl * 128 + 3 * 32 + lane] = anh;
            __syncthreads();
            if (khalf == 0) {
                ar  += sredf[512 + jl * 128 + 0 * 32 + lane];
                az  += sredf[512 + jl * 128 + 1 * 32 + lane];
                anx += sredf[512 + jl * 128 + 2 * 32 + lane];
                anh += sredf[512 + jl * 128 + 3 * 32 + lane];
                float r = 1.f / (1.f + expf(-(ar + bih1[j] + bhh1[j])));
                float z = 1.f / (1.f + expf(-(az + bih1[j + 512] + bhh1[j + 512])));
                float n = tanhf(anx + bih1[j + 1024] + r * (anh + bhh1[j + 1024]));
                float hp = h1pT[bid * 128 + lane * 4 + jl];
                float hnew = (1.f - z) * n + z * hp;
                h1nT[bid * 128 + lane * 4 + jl] = hnew;
                g_dc[((size_t)lane * Tn + t) * (2 * HIDn) + j] = hnew;
            }
        }
        gsync(++e);

        // ===== Phase 3: q = dec @ Wq^T (4 chunks) =====
        {
            if (tid == 0) {
                issue(G, h1nT); issue(G + 1, h1nT + 4096); issue(G + 2, h1nT + 8192);
            }
            float aq = 0.f;
            for (int c = 0; c < 4; c++) {
                int g = G + c, buf = g % 3;
                MBAR_WAIT(mb + buf * 8, (uint32_t)((g / 3) & 1));
                const float* sx = sXT + buf * 4096 + (khalf * 16) * 128 + lane * 4;
                single16T(sx, sWq + jl * 512 + c * 128 + khalf * 64, aq);
                __syncthreads();
                if (tid == 0 && c + 3 < 4) issue(G + c + 3, h1nT + (c + 3) * 4096);
            }
            G += 4;
            sredf[khalf * 512 + jl * 128 + lane] = aq;
            __syncthreads();
            if (khalf == 0) {
                aq += sredf[512 + jl * 128 + lane];
                g_q[lane * HIDn + j] = aq;
            }
        }
        gsync(++e);

        // ===== Phase 4: scores (HW tanh) =====
        {
#pragma unroll
            for (int r = 0; r < 2; r++) {
                int pi = bid * 16 + w * 2 + r;
                int b = pi >> 6, s = pi & 63;
                const float* qb = g_q + b * HIDn;
                const float* kp = g_kproj + ((size_t)b * Sn + s) * HIDn;
                float acc = 0.f;
#pragma unroll
                for (int i = 0; i < 16; i++) {
                    int h = lane + i * 32;
                    acc = fmaf(vvec[h], tanh_fast(qb[h] + kp[h]), acc);
                }
#pragma unroll
                for (int o = 16; o; o >>= 1) acc += __shfl_xor_sync(0xFFFFFFFFu, acc, o);
                if (lane == 0) g_e[b * Sn + s] = mask[b * Sn + s] ? -1e9f : acc;
            }
        }
        gsync(++e);

        // ===== Phase 5: softmax + ctx =====
        {
            const int b  = bid >> 2;
            const int hs = (bid & 3) * 128;
            if (w == 0) {
                float e0 = g_e[b * Sn + lane];
                float e1 = g_e[b * Sn + 32 + lane];
                float m = fmaxf(e0, e1);
#pragma unroll
                for (int o = 16; o; o >>= 1) m = fmaxf(m, __shfl_xor_sync(0xFFFFFFFFu, m, o));
                float x0 = expf(e0 - m), x1 = expf(e1 - m);
                float ssum = x0 + x1;
#pragma unroll
                for (int o = 16; o; o >>= 1) ssum += __shfl_xor_sync(0xFFFFFFFFu, ssum, o);
                float rinv = 1.f / ssum;
                sA[lane]      = x0 * rinv;
                sA[lane + 32] = x1 * rinv;
            }
            __syncthreads();
            if (tid < 128) {
                int h = hs + tid;
                const float* eb = enc + (size_t)b * Sn * HIDn + h;
                float c = 0.f;
#pragma unroll
                for (int s = 0; s < Sn; s++) c = fmaf(sA[s], eb[(size_t)s * HIDn], c);
                ctxnT[(h >> 2) * 128 + b * 4 + (h & 3)] = c;
                g_dc[((size_t)b * Tn + t) * (2 * HIDn) + HIDn + h] = c;
            }
        }
        gsync(++e);
    }
}

// ---------------- small fp32 GEMM for kproj ----------------
#define GBM 64
#define GBN 64
#define GBK 16
__global__ __launch_bounds__(256) void gemm_abt_kernel(
    const float* __restrict__ A, const float* __restrict__ B,
    float* __restrict__ C, int M, int N, int K)
{
    __shared__ __align__(16) float As[GBK][GBM + 4];
    __shared__ __align__(16) float Bs[GBK][GBN + 4];
    const int tid = threadIdx.x;
    const int rowBase = blockIdx.y * GBM;
    const int colBase = blockIdx.x * GBN;
    const int tm = tid >> 4;
    const int tn = tid & 15;
    const int lr  = tid >> 2;
    const int lk4 = (tid & 3) * 4;

    float acc[4][4];
#pragma unroll
    for (int i = 0; i < 4; i++)
#pragma unroll
        for (int jj = 0; jj < 4; jj++) acc[i][jj] = 0.f;

    const float* Aptr = A + (size_t)(rowBase + lr) * K + lk4;
    const float* Bptr = B + (size_t)(colBase + lr) * K + lk4;
    for (int kt = 0; kt < K; kt += GBK) {
        float4 a4 = *(const float4*)(Aptr + kt);
        float4 b4 = *(const float4*)(Bptr + kt);
        As[lk4 + 0][lr] = a4.x; As[lk4 + 1][lr] = a4.y;
        As[lk4 + 2][lr] = a4.z; As[lk4 + 3][lr] = a4.w;
        Bs[lk4 + 0][lr] = b4.x; Bs[lk4 + 1][lr] = b4.y;
        Bs[lk4 + 2][lr] = b4.z; Bs[lk4 + 3][lr] = b4.w;
        __syncthreads();
#pragma unroll
        for (int kk = 0; kk < GBK; kk++) {
            float4 av = *(const float4*)(&As[kk][tm * 4]);
            float4 bv = *(const float4*)(&Bs[kk][tn * 4]);
            float ar[4] = {av.x, av.y, av.z, av.w};
            float br[4] = {bv.x, bv.y, bv.z, bv.w};
#pragma unroll
            for (int i = 0; i < 4; i++)
#pragma unroll
                for (int jj = 0; jj < 4; jj++)
                    acc[i][jj] = fmaf(ar[i], br[jj], acc[i][jj]);
        }
        __syncthreads();
    }
#pragma unroll
    for (int i = 0; i < 4; i++) {
        float4 o;
        o.x = acc[i][0]; o.y = acc[i][1]; o.z = acc[i][2]; o.w = acc[i][3];
        *(float4*)(C + (size_t)(rowBase + tm * 4 + i) * N + colBase + tn * 4) = o;
    }
}

// ---------------- launch ----------------
extern "C" void kernel_launch(void* const* d_in, const int* in_sizes, int n_in,
                              void* d_out, int out_size)
{
    const float*         enc       = (const float*)d_in[0];
    const unsigned char* src_mask  = (const unsigned char*)d_in[1];
    const int*           tgt_in    = (const int*)d_in[2];
    const float*         emb_table = (const float*)d_in[3];
    const float*         W_ih0     = (const float*)d_in[4];
    const float*         W_hh0     = (const float*)d_in[5];
    const float*         b_ih0     = (const float*)d_in[6];
    const float*         b_hh0     = (const float*)d_in[7];
    const float*         W_ih1     = (const float*)d_in[8];
    const float*         W_hh1     = (const float*)d_in[9];
    const float*         b_ih1     = (const float*)d_in[10];
    const float*         b_hh1     = (const float*)d_in[11];
    const float*         Wq        = (const float*)d_in[12];
    const float*         Wk        = (const float*)d_in[13];
    const float*         vvec      = (const float*)d_in[14];
    const float*         W_out     = (const float*)d_in[15];
    const float*         b_out     = (const float*)d_in[16];
    float*               out       = (float*)d_out;

    float* kproj_ptr = nullptr;
    float* dc_ptr    = nullptr;
    __half *ah_p = nullptr;
    cudaGetSymbolAddress((void**)&kproj_ptr, g_kproj);
    cudaGetSymbolAddress((void**)&dc_ptr, g_dc);
    cudaGetSymbolAddress((void**)&ah_p, g_ah);

    const int smem_bytes = 2 * STGB;   // 65536
    cudaFuncSetAttribute(hmma_gemm_vocab,
                         cudaFuncAttributeMaxDynamicSharedMemorySize, smem_bytes);
    cudaFuncSetAttribute(decoder_persistent,
                         cudaFuncAttributeMaxDynamicSharedMemorySize, DEC_SMEM_B);

    // k_proj = enc_out @ Wk^T
    {
        dim3 grid(HIDn / GBN, (Bn * Sn) / GBM);
        gemm_abt_kernel<<<grid, 256>>>(enc, Wk, kproj_ptr, Bn * Sn, HIDn, HIDn);
    }

    // full recurrence (smem weights + TMA-bulk activation staging) + W-split
    decoder_persistent<<<NBLK + EXTRA, NTHR, DEC_SMEM_B>>>(
        enc, src_mask, tgt_in, emb_table,
        W_ih0, W_hh0, b_ih0, b_hh0,
        W_ih1, W_hh1, b_ih1, b_hh1,
        Wq, vvec, W_out);

    // split dc -> tiled/swizzled fp16 (hi only)
    {
        int nchunks = Bn * Tn * (KV / 8);
        split_h_kernel<<<(nchunks + 255) / 256, 256>>>(dc_ptr, ah_p, nchunks);
    }

    // logits via fp16 1-term HMMA GEMM
    {
        dim3 grid((Bn * Tn) / 128, VOCn / 128);
        hmma_gemm_vocab<<<grid, 256, smem_bytes>>>(b_out, out);
    }
}